// round 13
// baseline (speedup 1.0000x reference)
#include <cuda_runtime.h>
#include <cuda_bf16.h>
#include <math.h>
#include <stdint.h>

#define NN    64
#define KK    48
#define MM    (NN*KK)      // 3072
#define TOBS  30
#define PREDN 15
#define TSTEPS (TOBS+PREDN)  // 45, t runs 1..44
#define EMB   64
#define NODE  128
#define EDGE  256
#define CNN   512
#define GT    (4*NODE)     // 512
#define GN    (4*EDGE)     // 1024
#define CONC  (NODE+CNN+EDGE) // 896
#define NBLK  389

typedef unsigned long long ULL;

#define PK(d,s)   asm("mov.b64 %0, {%1, %1};" : "=l"(d) : "f"(s))
#define UPK(lo,hi,p) asm("mov.b64 {%0, %1}, %2;" : "=f"(lo), "=f"(hi) : "l"(p))
#define FMA2(c,a,b) asm("fma.rn.f32x2 %0, %1, %2, %0;" : "+l"(c) : "l"(a), "l"(b))

__device__ __forceinline__ uint32_t smem_u32(const void* p){
    uint32_t a; asm("{ .reg .u64 t; cvta.to.shared.u64 t, %1; cvt.u32.u64 %0, t; }" : "=r"(a) : "l"(p)); return a;
}
#define LDMX4(r0,r1,r2,r3,addr) \
    asm volatile("ldmatrix.sync.aligned.m8n8.x4.shared.b16 {%0,%1,%2,%3}, [%4];" \
        : "=r"(r0), "=r"(r1), "=r"(r2), "=r"(r3) : "r"(addr))
#define MMA16816(c,a0,a1,a2,a3,b0,b1) \
    asm volatile("mma.sync.aligned.m16n8k16.row.col.f32.bf16.bf16.f32 " \
        "{%0,%1,%2,%3}, {%4,%5,%6,%7}, {%8,%9}, {%0,%1,%2,%3};" \
        : "+f"((c)[0]), "+f"((c)[1]), "+f"((c)[2]), "+f"((c)[3]) \
        : "r"(a0), "r"(a1), "r"(a2), "r"(a3), "r"(b0), "r"(b1))
#define CPA16(dst,src) \
    asm volatile("cp.async.cg.shared.global [%0], [%1], 16;" :: "r"(dst), "l"(src))
#define CPA8(dst,src) \
    asm volatile("cp.async.ca.shared.global [%0], [%1], 8;" :: "r"(dst), "l"(src))
#define CPA4(dst,src) \
    asm volatile("cp.async.ca.shared.global [%0], [%1], 4;" :: "r"(dst), "l"(src))
#define CPCOMMIT() asm volatile("cp.async.commit_group;")
#define CPWAIT(n)  asm volatile("cp.async.wait_group %0;" :: "n"(n))

// ---------------- persistent device state ----------------
__device__ float d_thtT[2][NODE*NN];
__device__ float d_thtNM[NN*NODE];
__device__ float d_tct[NN*NODE];
__device__ __nv_bfloat16 d_nhHi[2][MM*EDGE];
__device__ __nv_bfloat16 d_nhLo[2][MM*EDGE];
__device__ float d_nct[MM*EDGE];
__device__ float d_Ht[NN*EDGE];
__device__ float d_HtaP[2][NN*EDGE];
__device__ float d_cabs[NN*2], d_crel[NN*2];
__device__ float d_cstepP[2][NN*2];
__device__ int   d_flag;
__device__ int   d_mnt;
// fine-grained completion flags: [t][rowTile*16+colTile]
__device__ int   d_rcDone[TSTEPS][24*16];
__device__ int   d_tgtCnt[TSTEPS];
__device__ int   d_epiCnt[TSTEPS];
__device__ int   d_gateTt[TSTEPS];
__device__ int   d_gateNt[TSTEPS];
__device__ float d_currNt[TSTEPS];
// weights
__device__ __nv_bfloat16 d_WNHi[GN*EDGE];
__device__ __nv_bfloat16 d_WNLo[GN*EDGE];
__device__ float d_WhhTT[NODE*GT];
__device__ float d_WxN[GN*2], d_bN[GN];
__device__ float d_WxT[GT*2], d_bT[GT];
__device__ float d_imgpart[NN*2];

__device__ __forceinline__ float sigm(float x){ return 1.f/(1.f+expf(-x)); }
__device__ __forceinline__ void wait_ge(volatile int* p, int v){
    while(*p < v){ __nanosleep(64); }
}
__device__ __forceinline__ void wait_pair(volatile int* f){
    while(f[0]==0 || f[1]==0){ __nanosleep(64); }
}

// dynamic smem layout
#define OFF_AHI 0
#define OFF_ALO 10240
#define OFF_BHI 20480
#define OFF_BLO 25600
#define BUF     30720
#define OFF_EPN 61440
#define OFF_EPS 69632
#define OFF_EPH 70656
#define OFF_W   71168
#define DSMEM_TOTAL 71680

// ---------------- init kernels ----------------
__global__ void k_zero(){
    long i0 = (long)blockIdx.x*blockDim.x + threadIdx.x;
    long st = (long)gridDim.x*blockDim.x;
    uint32_t* hh = (uint32_t*)&d_nhHi[0][0];
    uint32_t* hl = (uint32_t*)&d_nhLo[0][0];
    for(long i=i0;i<(long)MM*EDGE;i+=st){ hh[i]=0u; hl[i]=0u; }
    for(long i=i0;i<(long)MM*EDGE;i+=st) d_nct[i]=0.f;
    float* th = &d_thtT[0][0];
    for(long i=i0;i<2L*NN*NODE;i+=st) th[i]=0.f;
    for(long i=i0;i<(long)NN*NODE;i+=st){ d_tct[i]=0.f; d_thtNM[i]=0.f; }
    for(long i=i0;i<(long)NN*EDGE;i+=st){ d_Ht[i]=0.f; d_HtaP[0][i]=0.f; d_HtaP[1][i]=0.f; }
    if(i0<NN*2){ d_cabs[i0]=0.f; d_crel[i0]=0.f; d_cstepP[0][i0]=0.f; d_cstepP[1][i0]=0.f; }
    for(long i=i0;i<(long)TSTEPS*24*16;i+=st) ((int*)d_rcDone)[i]=0;
    for(long i=i0;i<TSTEPS;i+=st){ d_tgtCnt[i]=0; d_epiCnt[i]=0; }
    if(i0==0){ d_flag=0; d_mnt=0; }
}

__global__ void k_tables(const int* __restrict__ thist, const int* __restrict__ nhist){
    int t = blockIdx.x + 1;
    int tid = threadIdx.x;
    __shared__ int s_cnt[256];
    __shared__ int s_any[256];
    int cnt=0, any=0;
    if(t < TOBS){
        for(int m=tid;m<MM;m+=256) cnt += (nhist[m] > (TOBS - t)) ? 1 : 0;
        for(int n=tid;n<NN;n+=256) any |= (thist[n] > (TOBS - t)) ? 1 : 0;
    }else{
        cnt = (tid==0)?MM:0; any = 1;
    }
    s_cnt[tid]=cnt; s_any[tid]=any;
    __syncthreads();
    for(int o=128;o>0;o>>=1){
        if(tid<o){ s_cnt[tid]+=s_cnt[tid+o]; s_any[tid]|=s_any[tid+o]; }
        __syncthreads();
    }
    if(tid==0){
        int gt = s_any[0]?1:0;
        int cn = s_cnt[0];
        d_gateTt[t]=gt; d_gateNt[t]=(gt && cn>0)?1:0; d_currNt[t]=(float)cn;
    }
}

__global__ void k_prep(const float* __restrict__ Whh_n, const float* __restrict__ Wih_n,
                       const float* __restrict__ bih_n, const float* __restrict__ bhh_n,
                       const float* __restrict__ Whh_t, const float* __restrict__ Wih_t,
                       const float* __restrict__ bih_t, const float* __restrict__ bhh_t,
                       const float* __restrict__ W_disp, const float* __restrict__ b_disp,
                       const float* __restrict__ img, const float* __restrict__ W_pred){
    int i0 = blockIdx.x*blockDim.x + threadIdx.x;
    int st = gridDim.x*blockDim.x;
    for(int i=i0;i<GN*EDGE;i+=st){
        int g=i/EDGE, k=i%EDGE; int e=g>>2, q=g&3;
        float v = Whh_n[(q*EDGE+e)*EDGE + k];
        __nv_bfloat16 hi = __float2bfloat16(v);
        d_WNHi[i] = hi;
        d_WNLo[i] = __float2bfloat16(v - __bfloat162float(hi));
    }
    for(int i=i0;i<NODE*GT;i+=st){
        int k=i/GT, g=i%GT; int e=g>>2, q=g&3;
        d_WhhTT[i] = Whh_t[(q*NODE+e)*NODE + k];
    }
    for(int r=i0;r<GN;r+=st){
        int e=r>>2, q=r&3; int o=q*EDGE+e;
        float w0=0.f,w1=0.f,bb=bih_n[o]+bhh_n[o];
        for(int d=0;d<EMB;d++){
            float wi=Wih_n[o*EMB+d];
            w0+=wi*W_disp[d*2]; w1+=wi*W_disp[d*2+1]; bb+=wi*b_disp[d];
        }
        d_WxN[r*2]=w0; d_WxN[r*2+1]=w1; d_bN[r]=bb;
    }
    for(int r=i0;r<GT;r+=st){
        int e=r>>2, q=r&3; int o=q*NODE+e;
        float w0=0.f,w1=0.f,bb=bih_t[o]+bhh_t[o];
        for(int d=0;d<EMB;d++){
            float wi=Wih_t[o*EMB+d];
            w0+=wi*W_disp[d*2]; w1+=wi*W_disp[d*2+1]; bb+=wi*b_disp[d];
        }
        d_WxT[r*2]=w0; d_WxT[r*2+1]=w1; d_bT[r]=bb;
    }
    for(int i=i0;i<NN*2;i+=st){
        int n=i>>1, j=i&1; float s=0.f;
        for(int c=0;c<CNN;c++) s += img[n*CNN+c]*W_pred[j*CONC + NODE + c];
        d_imgpart[i]=s;
    }
}

__device__ __forceinline__ void prefetch_chunk(uint32_t uS, uint32_t bo,
    const __nv_bfloat16* __restrict__ hHi, const __nv_bfloat16* __restrict__ hLo,
    int m0, int g0, int k0, int tid)
{
    #pragma unroll
    for(int g=0;g<2;g++){
        int j = tid + g*256;
        int row = j>>2, c16 = j&3;
        uint32_t d = bo + (uint32_t)(row*80 + c16*16);
        long soff = (long)(m0+row)*EDGE + k0 + c16*8;
        CPA16(uS + OFF_AHI + d, hHi + soff);
        CPA16(uS + OFF_ALO + d, hLo + soff);
    }
    {
        int row = tid>>2, c16 = tid&3;
        uint32_t d = bo + (uint32_t)(row*80 + c16*16);
        long soff = (long)(g0+row)*EDGE + k0 + c16*8;
        CPA16(uS + OFF_BHI + d, d_WNHi + soff);
        CPA16(uS + OFF_BLO + d, d_WNLo + soff);
    }
    CPCOMMIT();
}

__device__ __forceinline__ void prefetch_ep(uint32_t uS,
    const float* __restrict__ nstep_in, const int* __restrict__ nhist,
    int m0, int e0c, int tc, int tid)
{
    #pragma unroll
    for(int g=0;g<2;g++){
        int idx = tid + g*256;
        int row = idx>>2, q = idx&3;
        CPA16(uS + OFF_EPN + (uint32_t)(row*64 + q*16),
              &d_nct[(long)(m0+row)*EDGE + e0c + q*4]);
    }
    if(tid < 128){
        CPA8(uS + OFF_EPS + (uint32_t)(tid*8), &nstep_in[((m0+tid)*TOBS+tc)*2]);
        CPA4(uS + OFF_EPH + (uint32_t)(tid*4), &nhist[m0+tid]);
    }
}

// per-block attention weights for this tile's rows -> s_w[128]
__device__ void compute_w(float* s_w, int m0, int t, bool obs, int tc,
    const float* __restrict__ trel, const float* __restrict__ tabs,
    const float* __restrict__ nabs_in, const int* __restrict__ nhist,
    const float* __restrict__ W_att_t, const float* __restrict__ b_att_t,
    const float* __restrict__ W_att_n, const float* __restrict__ b_att_n,
    int wid, int lane)
{
    if(wid >= 4) return;
    int n = m0/KK + wid;
    if(n >= NN || n*KK >= m0+128) return;
    float currNf = d_currNt[t];
    float crel0,crel1,cab0,cab1;
    if(obs){
        int o2 = (n*TOBS+t)*2;
        crel0=trel[o2]; crel1=trel[o2+1];
        cab0 =tabs[o2]; cab1 =tabs[o2+1];
    }else{
        crel0=d_crel[n*2]; crel1=d_crel[n*2+1];
        cab0 =d_cabs[n*2]; cab1 =d_cabs[n*2+1];
    }
    float p0=0.f,p1=0.f,p2=0.f;
    #pragma unroll
    for(int a=lane;a<64;a+=32){
        float atv = W_att_t[a*2]*crel0 + W_att_t[a*2+1]*crel1 + b_att_t[a];
        p0 += atv*W_att_n[a*2];
        p1 += atv*W_att_n[a*2+1];
        p2 += atv*b_att_n[a];
    }
    #pragma unroll
    for(int o=1;o<32;o<<=1){
        p0 += __shfl_xor_sync(0xffffffffu,p0,o);
        p1 += __shfl_xor_sync(0xffffffffu,p1,o);
        p2 += __shfl_xor_sync(0xffffffffu,p2,o);
    }
    int m1 = n*KK + lane;
    int off1 = (m1*TOBS+tc)*2;
    float dx1 = nabs_in[off1]-cab0, dy1 = nabs_in[off1+1]-cab1;
    float mv1 = obs ? ((nhist[m1] > (TOBS - t)) ? 1.f : 0.f) : 1.f;
    float s0v = (dx1*p0+dy1*p1+p2)*currNf*0.125f*mv1;
    float s1v = -1e30f, mv2 = 0.f; int m2 = 0;
    if(lane < 16){
        m2 = n*KK + 32 + lane;
        int off2 = (m2*TOBS+tc)*2;
        float dx2 = nabs_in[off2]-cab0, dy2 = nabs_in[off2+1]-cab1;
        mv2 = obs ? ((nhist[m2] > (TOBS - t)) ? 1.f : 0.f) : 1.f;
        s1v = (dx2*p0+dy2*p1+p2)*currNf*0.125f*mv2;
    }
    float mx = fmaxf(s0v, s1v);
    #pragma unroll
    for(int o=1;o<32;o<<=1) mx = fmaxf(mx, __shfl_xor_sync(0xffffffffu,mx,o));
    float e0v = expf(s0v-mx)*mv1;
    float e1v = (lane<16) ? expf(s1v-mx)*mv2 : 0.f;
    float dn = e0v + e1v;
    #pragma unroll
    for(int o=1;o<32;o<<=1) dn += __shfl_xor_sync(0xffffffffu,dn,o);
    dn += 1e-6f;
    int r1 = m1 - m0;
    if(r1>=0 && r1<128) s_w[r1] = e0v/dn;
    if(lane<16){
        int r2 = m2 - m0;
        if(r2>=0 && r2<128) s_w[r2] = e1v/dn;
    }
}

// =========================================================================
__global__ void __launch_bounds__(256,3) k_run(
    const float* __restrict__ tabs, const float* __restrict__ trel, const float* __restrict__ tstep,
    const float* __restrict__ nabs_in, const float* __restrict__ nstep_in,
    const int* __restrict__ thist, const int* __restrict__ nhist,
    const float* __restrict__ W_att_t, const float* __restrict__ b_att_t,
    const float* __restrict__ W_att_n, const float* __restrict__ b_att_n,
    const float* __restrict__ W_pred, const float* __restrict__ b_pred,
    float* __restrict__ out)
{
    extern __shared__ __align__(128) char dsm[];
    const int bx = blockIdx.x;
    const int tid = threadIdx.x;

    const int bi = bx-1;
    const int rowTile = (bi>=0) ? (bi % 24) : 0;
    const int colTile = (bi>=0) ? (bi / 24) : 0;
    const int m0 = rowTile*128, g0 = colTile*64, e0c = colTile*16;
    const int wid = tid>>5, lane = tid&31;
    const int tig = lane&3, gid = lane>>2;
    const int wm = wid&3, wn = wid>>2;
    const uint32_t uS = smem_u32(dsm);
    const uint32_t aHiO = OFF_AHI + (uint32_t)((wm*32 + (lane&15))*80) + (uint32_t)((lane>>4)*16);
    const uint32_t aLoO = OFF_ALO + (uint32_t)((wm*32 + (lane&15))*80) + (uint32_t)((lane>>4)*16);
    const uint32_t bHiO = OFF_BHI + (uint32_t)((wn*32 + (lane&15))*80) + (uint32_t)((lane>>4)*16);
    const uint32_t bLoO = OFF_BLO + (uint32_t)((wn*32 + (lane&15))*80) + (uint32_t)((lane>>4)*16);
    float* sC  = (float*)dsm;
    float* sWh = (float*)(dsm + 34816);
    float* s_w = (float*)(dsm + OFF_W);

    for(int t=1; t<TSTEPS; t++){
        const int cur=(t-1)&1, nxt=t&1;
        const bool obs = (t < TOBS);
        const int tc = obs ? t : (TOBS-1);

        if(bx == 0){
            __shared__ float s_pred[NN*2];
            if(!obs){
                if(tid==0){
                    wait_ge(&d_epiCnt[t-1], 384);
                    wait_ge(&d_tgtCnt[t-1], 4);
                }
                __syncthreads();
                __threadfence();
                {
                    int gp = d_gateNt[t-1];
                    float4* Ht4 = (float4*)d_Ht;
                    float4* Ha4 = (float4*)d_HtaP[(t-1)&1];
                    for(int i=tid;i<NN*EDGE/4;i+=256){
                        if(gp) Ht4[i]=Ha4[i];
                        Ha4[i]=make_float4(0.f,0.f,0.f,0.f);
                    }
                }
                __threadfence();
                __syncthreads();
                if(tid==0) atomicExch(&d_mnt, t-1);
                {
                    int item = tid>>1, sub = tid&1;
                    int n = item>>1, j = item&1;
                    const float4* th4 = (const float4*)&d_thtNM[n*NODE + sub*64];
                    const float4* wp1 = (const float4*)&W_pred[j*CONC + sub*64];
                    float acc = 0.f;
                    #pragma unroll
                    for(int i=0;i<16;i++){
                        float4 a=th4[i], b=wp1[i];
                        acc += a.x*b.x + a.y*b.y + a.z*b.z + a.w*b.w;
                    }
                    const float4* hh4 = (const float4*)&d_Ht[n*EDGE + sub*128];
                    const float4* wp3 = (const float4*)&W_pred[j*CONC + NODE+CNN + sub*128];
                    #pragma unroll
                    for(int i=0;i<32;i++){
                        float4 a=hh4[i], b=wp3[i];
                        acc += a.x*b.x + a.y*b.y + a.z*b.z + a.w*b.w;
                    }
                    acc += __shfl_xor_sync(0xffffffffu, acc, 1);
                    if(sub==0) s_pred[item] = acc + d_imgpart[item] + b_pred[j];
                }
                __syncthreads();
                if(tid<NN*2){
                    float p=s_pred[tid];
                    d_cabs[tid]+=p;
                    float cr=d_crel[tid]+p; d_crel[tid]=cr;
                    d_cstepP[t&1][tid]=p;
                    int n=tid>>1, j=tid&1;
                    out[(n*PREDN + (t-TOBS))*2 + j] = cr;
                }
                __threadfence();
                __syncthreads();
                if(tid==0) atomicExch(&d_flag, t);
            }else{
                if(t==TOBS-1 && tid<NN*2){
                    int n=tid>>1, j=tid&1; int off=(n*TOBS+t)*2+j;
                    d_cabs[tid]=tabs[off]; d_crel[tid]=trel[off];
                }
                if(t>=2){
                    if(tid==0) wait_ge(&d_epiCnt[t-1], 384);
                    __syncthreads();
                    __threadfence();
                    int gp = d_gateNt[t-1];
                    float4* Ht4 = (float4*)d_Ht;
                    float4* Ha4 = (float4*)d_HtaP[(t-1)&1];
                    for(int i=tid;i<NN*EDGE/4;i+=256){
                        if(gp) Ht4[i]=Ha4[i];
                        Ha4[i]=make_float4(0.f,0.f,0.f,0.f);
                    }
                    __threadfence();
                    __syncthreads();
                    if(tid==0) atomicExch(&d_mnt, t-1);
                }
            }
        }
        else if(bx <= 384){
            int gate_n = d_gateNt[t];
            if(!gate_n){
                // self-dependent skip path (own slice only): no wait needed
                int row = tid>>1, half = tid&1;
                long base = (long)(m0+row)*EDGE + e0c + half*8;
                *(uint4*)&d_nhHi[nxt][base] = *(const uint4*)&d_nhHi[cur][base];
                *(uint4*)&d_nhLo[nxt][base] = *(const uint4*)&d_nhLo[cur][base];
                __threadfence();
                __syncthreads();
                if(tid==0){
                    atomicExch(&d_rcDone[t][rowTile*16+colTile], 1);
                    atomicAdd(&d_epiCnt[t], 1);
                }
                continue;
            }
            const __nv_bfloat16* hHi = d_nhHi[cur];
            const __nv_bfloat16* hLo = d_nhLo[cur];
            volatile int* fl = (volatile int*)&d_rcDone[t-1][rowTile*16];
            float C[2][4][4];
            #pragma unroll
            for(int mi=0;mi<2;mi++)
                #pragma unroll
                for(int j=0;j<4;j++){ C[mi][j][0]=0.f; C[mi][j][1]=0.f; C[mi][j][2]=0.f; C[mi][j][3]=0.f; }

            prefetch_ep(uS, nstep_in, nhist, m0, e0c, tc, tid);   // self-written data, no wait
            if(t>=2){ wait_pair(fl + 0); __threadfence(); }       // chunk0 needs colTiles 0,1
            prefetch_chunk(uS, 0u, hHi, hLo, m0, g0, 0, tid);
            if(obs)
                compute_w(s_w, m0, t, true, tc, trel, tabs, nabs_in, nhist,
                          W_att_t, b_att_t, W_att_n, b_att_n, wid, lane);
            #pragma unroll
            for(int ch=0; ch<8; ch++){
                uint32_t bo = (ch&1)*BUF;
                if(ch<7){
                    if(t>=2){ wait_pair(fl + 2*(ch+1)); __threadfence(); }
                    prefetch_chunk(uS, ((ch+1)&1)*BUF, hHi, hLo, m0, g0, (ch+1)*32, tid);
                    CPWAIT(1);
                }else{
                    CPWAIT(0);
                }
                __syncthreads();
                #pragma unroll
                for(int ktl=0; ktl<2; ktl++){
                    uint32_t koff = bo + ktl*32;
                    uint32_t ah[2][4], al[2][4];
                    #pragma unroll
                    for(int mi=0;mi<2;mi++){
                        LDMX4(ah[mi][0],ah[mi][1],ah[mi][2],ah[mi][3], uS + aHiO + (uint32_t)(mi*16*80) + koff);
                        LDMX4(al[mi][0],al[mi][1],al[mi][2],al[mi][3], uS + aLoO + (uint32_t)(mi*16*80) + koff);
                    }
                    #pragma unroll
                    for(int ng=0; ng<2; ng++){
                        uint32_t bh0,bh1,bh2,bh3, bl0,bl1,bl2,bl3;
                        LDMX4(bh0,bh1,bh2,bh3, uS + bHiO + (uint32_t)(ng*16*80) + koff);
                        LDMX4(bl0,bl1,bl2,bl3, uS + bLoO + (uint32_t)(ng*16*80) + koff);
                        MMA16816(C[0][ng*2],   ah[0][0],ah[0][1],ah[0][2],ah[0][3], bh0,bh2);
                        MMA16816(C[0][ng*2+1], ah[0][0],ah[0][1],ah[0][2],ah[0][3], bh1,bh3);
                        MMA16816(C[1][ng*2],   ah[1][0],ah[1][1],ah[1][2],ah[1][3], bh0,bh2);
                        MMA16816(C[1][ng*2+1], ah[1][0],ah[1][1],ah[1][2],ah[1][3], bh1,bh3);
                        MMA16816(C[0][ng*2],   ah[0][0],ah[0][1],ah[0][2],ah[0][3], bl0,bl2);
                        MMA16816(C[0][ng*2+1], ah[0][0],ah[0][1],ah[0][2],ah[0][3], bl1,bl3);
                        MMA16816(C[1][ng*2],   ah[1][0],ah[1][1],ah[1][2],ah[1][3], bl0,bl2);
                        MMA16816(C[1][ng*2+1], ah[1][0],ah[1][1],ah[1][2],ah[1][3], bl1,bl3);
                        MMA16816(C[0][ng*2],   al[0][0],al[0][1],al[0][2],al[0][3], bh0,bh2);
                        MMA16816(C[0][ng*2+1], al[0][0],al[0][1],al[0][2],al[0][3], bh1,bh3);
                        MMA16816(C[1][ng*2],   al[1][0],al[1][1],al[1][2],al[1][3], bh0,bh2);
                        MMA16816(C[1][ng*2+1], al[1][0],al[1][1],al[1][2],al[1][3], bh1,bh3);
                    }
                }
                __syncthreads();
            }

            #pragma unroll
            for(int mi=0;mi<2;mi++){
                int r0 = wm*32 + mi*16 + gid;
                #pragma unroll
                for(int jj=0;jj<4;jj++){
                    int col = wn*32 + jj*8 + tig*2;
                    *(float2*)&sC[r0*68+col]     = make_float2(C[mi][jj][0],C[mi][jj][1]);
                    *(float2*)&sC[(r0+8)*68+col] = make_float2(C[mi][jj][2],C[mi][jj][3]);
                }
            }
            if(!obs){
                if(tid==0) wait_ge(&d_flag, t);
                __syncthreads();
                __threadfence();
                compute_w(s_w, m0, t, false, tc, trel, tabs, nabs_in, nhist,
                          W_att_t, b_att_t, W_att_n, b_att_n, wid, lane);
            }
            if(tid==0 && t>=3) wait_ge(&d_mnt, t-2);
            __syncthreads();
            __threadfence();

            {
                int row = tid>>1, half = tid&1;
                int m = m0 + row;
                long base = (long)m*EDGE + e0c + half*8;
                float2 xv = *(const float2*)(dsm + OFF_EPS + row*8);
                int hist = *(const int*)(dsm + OFF_EPH + row*4);
                bool mv = obs ? (hist > (TOBS - t)) : true;
                bool un = mv;
                float wv = s_w[row];
                const float* sn = (const float*)(dsm + OFF_EPN + row*64 + half*32);
                float coldA[8];
                #pragma unroll
                for(int cc=0;cc<8;cc++) coldA[cc]=sn[cc];
                const float* g4p = &sC[row*68 + half*32];
                float hnew[8], cnew[8];
                #pragma unroll
                for(int cc=0;cc<8;cc++){
                    int gb = g0 + half*32 + cc*4;
                    float4 wA = *(const float4*)&d_WxN[gb*2];
                    float4 wB = *(const float4*)&d_WxN[gb*2+4];
                    float4 bb = *(const float4*)&d_bN[gb];
                    float gi_ = g4p[4*cc+0] + xv.x*wA.x + xv.y*wA.y + bb.x;
                    float gf  = g4p[4*cc+1] + xv.x*wA.z + xv.y*wA.w + bb.y;
                    float gg  = g4p[4*cc+2] + xv.x*wB.x + xv.y*wB.y + bb.z;
                    float go  = g4p[4*cc+3] + xv.x*wB.z + xv.y*wB.w + bb.w;
                    float c2 = sigm(gf)*coldA[cc] + sigm(gi_)*tanhf(gg);
                    hnew[cc] = sigm(go)*tanhf(c2);
                    cnew[cc] = un ? c2 : coldA[cc];
                }
                __align__(16) __nv_bfloat16 hb[8], lb[8];
                if(un){
                    #pragma unroll
                    for(int cc=0;cc<8;cc++){
                        hb[cc] = __float2bfloat16(hnew[cc]);
                        lb[cc] = __float2bfloat16(hnew[cc] - __bfloat162float(hb[cc]));
                    }
                }else{
                    *(uint4*)hb = *(const uint4*)&hHi[base];
                    *(uint4*)lb = *(const uint4*)&hLo[base];
                    #pragma unroll
                    for(int cc=0;cc<8;cc++)
                        hnew[cc] = __bfloat162float(hb[cc]) + __bfloat162float(lb[cc]);
                }
                *(uint4*)&d_nhHi[nxt][base] = *(uint4*)hb;
                *(uint4*)&d_nhLo[nxt][base] = *(uint4*)lb;
                *(float4*)&d_nct[base]   = make_float4(cnew[0],cnew[1],cnew[2],cnew[3]);
                *(float4*)&d_nct[base+4] = make_float4(cnew[4],cnew[5],cnew[6],cnew[7]);
                float* wout = &sWh[row*16 + half*8];
                *(float4*)&wout[0] = make_float4(wv*hnew[0],wv*hnew[1],wv*hnew[2],wv*hnew[3]);
                *(float4*)&wout[4] = make_float4(wv*hnew[4],wv*hnew[5],wv*hnew[6],wv*hnew[7]);
            }
            __syncthreads();
            if(tid < 64){
                int gi = tid>>4, col = tid&15;
                int n = m0/KK + gi;
                int lo = n*KK - m0; if(lo<0) lo=0;
                int hi2 = n*KK + KK - m0; if(hi2>128) hi2=128;
                if(lo < hi2 && n < NN){
                    float s=0.f;
                    for(int r=lo;r<hi2;r++) s += sWh[r*16+col];
                    atomicAdd(&d_HtaP[t&1][n*EDGE + e0c + col], s);
                }
            }
            __threadfence();
            __syncthreads();
            if(tid==0){
                atomicExch(&d_rcDone[t][rowTile*16+colTile], 1);
                atomicAdd(&d_epiCnt[t], 1);
            }
        }
        else{
            if(t>=2){
                if(tid==0) wait_ge(&d_tgtCnt[t-1], 4);
                __syncthreads();
                __threadfence();
            }
            int bj = bx - 385;
            int gate_t = d_gateTt[t];
            if(!gate_t){
                int e0 = bj*32;
                for(int i=tid;i<32*NN;i+=256){
                    int e = e0 + (i>>6), n = i&63;
                    d_thtT[nxt][e*NN+n] = d_thtT[cur][e*NN+n];
                }
                __threadfence();
                __syncthreads();
                if(tid==0) atomicAdd(&d_tgtCnt[t], 1);
                continue;
            }
            float (*As)[68]  = (float(*)[68]) (dsm);
            float (*Bs)[140] = (float(*)[140])(dsm + sizeof(float)*32*68);
            int g0t = bj*128, e0 = bj*32;
            const float* A = d_thtT[cur];
            int ty = tid>>4, tx = tid&15;
            int pb = tx*8; pb += (pb>>5)<<2;
            ULL accp[4][4];
            #pragma unroll
            for(int i=0;i<4;i++){
                #pragma unroll
                for(int j=0;j<4;j++) accp[i][j]=0ull;
            }
            for(int kt=0; kt<NODE; kt+=32){
                #pragma unroll
                for(int g=0;g<2;g++){
                    int idx = tid + g*256;
                    int k = idx>>4, nq = (idx&15)*4;
                    *(float4*)&As[k][nq] = *(const float4*)&A[(kt+k)*NN + nq];
                }
                #pragma unroll
                for(int g=0;g<4;g++){
                    int idx = tid + g*256;
                    int k = idx>>5, cq = (idx&31)*4;
                    int pc = cq + ((cq>>5)<<2);
                    *(float4*)&Bs[k][pc] = *(const float4*)&d_WhhTT[(kt+k)*GT + g0t+cq];
                }
                __syncthreads();
                #pragma unroll
                for(int k=0;k<32;k++){
                    float4 a0 = *(const float4*)&As[k][ty*4];
                    ulonglong2 bb0 = *(const ulonglong2*)&Bs[k][pb];
                    ulonglong2 bb1 = *(const ulonglong2*)&Bs[k][pb+4];
                    ULL ap;
                    PK(ap,a0.x); FMA2(accp[0][0],ap,bb0.x); FMA2(accp[0][1],ap,bb0.y); FMA2(accp[0][2],ap,bb1.x); FMA2(accp[0][3],ap,bb1.y);
                    PK(ap,a0.y); FMA2(accp[1][0],ap,bb0.x); FMA2(accp[1][1],ap,bb0.y); FMA2(accp[1][2],ap,bb1.x); FMA2(accp[1][3],ap,bb1.y);
                    PK(ap,a0.z); FMA2(accp[2][0],ap,bb0.x); FMA2(accp[2][1],ap,bb0.y); FMA2(accp[2][2],ap,bb1.x); FMA2(accp[2][3],ap,bb1.y);
                    PK(ap,a0.w); FMA2(accp[3][0],ap,bb0.x); FMA2(accp[3][1],ap,bb0.y); FMA2(accp[3][2],ap,bb1.x); FMA2(accp[3][3],ap,bb1.y);
                }
                __syncthreads();
            }
            if(!obs){
                if(tid==0){ wait_ge(&d_flag, t); }
                __syncthreads();
                __threadfence();
            }
            #pragma unroll
            for(int i=0;i<4;i++){
                int n = ty*4 + i;
                float x0, x1;
                if(obs){ int o2=(n*TOBS+t)*2; x0=tstep[o2]; x1=tstep[o2+1]; }
                else   { x0=d_cstepP[t&1][n*2]; x1=d_cstepP[t&1][n*2+1]; }
                bool tm = obs ? (thist[n] > (TOBS - t)) : true;
                #pragma unroll
                for(int c=0;c<2;c++){
                    float g4[4];
                    UPK(g4[0],g4[1],accp[i][c*2]);
                    UPK(g4[2],g4[3],accp[i][c*2+1]);
                    int rr = g0t + tx*8 + c*4;
                    #pragma unroll
                    for(int q=0;q<4;q++)
                        g4[q] += x0*d_WxT[(rr+q)*2] + x1*d_WxT[(rr+q)*2+1] + d_bT[rr+q];
                    float ig=sigm(g4[0]), fg=sigm(g4[1]), gg=tanhf(g4[2]), og=sigm(g4[3]);
                    int e = e0 + tx*2 + c;
                    float cold = d_tct[n*NODE+e];
                    float c2 = fg*cold + ig*gg;
                    float h2 = og*tanhf(c2);
                    bool un = tm;
                    float hv;
                    if(un){ d_tct[n*NODE+e]=c2; hv=h2; }
                    else  { hv = d_thtT[cur][e*NN+n]; }
                    d_thtT[nxt][e*NN+n]=hv;
                    d_thtNM[n*NODE+e]=hv;
                }
            }
            __threadfence();
            __syncthreads();
            if(tid==0) atomicAdd(&d_tgtCnt[t], 1);
        }
    }
}

// ---------------- launch ----------------
extern "C" void kernel_launch(void* const* d_in, const int* in_sizes, int n_in,
                              void* d_out, int out_size)
{
    const float* img    = (const float*)d_in[0];
    const float* tabs   = (const float*)d_in[1];
    const float* trel   = (const float*)d_in[2];
    const float* tstep  = (const float*)d_in[3];
    const float* nabs   = (const float*)d_in[4];
    const float* nstep  = (const float*)d_in[6];
    const int*   thist  = (const int*)d_in[7];
    const int*   nhist  = (const int*)d_in[8];
    const float* W_disp = (const float*)d_in[9];
    const float* b_disp = (const float*)d_in[10];
    const float* Wih_t  = (const float*)d_in[11];
    const float* Whh_t  = (const float*)d_in[12];
    const float* bih_t  = (const float*)d_in[13];
    const float* bhh_t  = (const float*)d_in[14];
    const float* Wih_n  = (const float*)d_in[15];
    const float* Whh_n  = (const float*)d_in[16];
    const float* bih_n  = (const float*)d_in[17];
    const float* bhh_n  = (const float*)d_in[18];
    const float* W_att_t= (const float*)d_in[19];
    const float* b_att_t= (const float*)d_in[20];
    const float* W_att_n= (const float*)d_in[21];
    const float* b_att_n= (const float*)d_in[22];
    const float* W_pred = (const float*)d_in[23];
    const float* b_pred = (const float*)d_in[24];
    float* out = (float*)d_out;

    static int s_attr_done = 0;
    if(!s_attr_done){
        cudaFuncSetAttribute(k_run, cudaFuncAttributeMaxDynamicSharedMemorySize, DSMEM_TOTAL);
        s_attr_done = 1;
    }

    k_zero<<<256,256>>>();
    k_tables<<<TSTEPS-1,256>>>(thist,nhist);
    k_prep<<<256,256>>>(Whh_n,Wih_n,bih_n,bhh_n,Whh_t,Wih_t,bih_t,bhh_t,
                        W_disp,b_disp,img,W_pred);
    k_run<<<NBLK,256,DSMEM_TOTAL>>>(tabs,trel,tstep,nabs,nstep,thist,nhist,
                        W_att_t,b_att_t,W_att_n,b_att_n,W_pred,b_pred,out);
}

// round 14
// speedup vs baseline: 1.1285x; 1.1285x over previous
#include <cuda_runtime.h>
#include <cuda_bf16.h>
#include <math.h>
#include <stdint.h>

#define NN    64
#define KK    48
#define MM    (NN*KK)      // 3072
#define TOBS  30
#define PREDN 15
#define TSTEPS (TOBS+PREDN)  // 45, t runs 1..44
#define EMB   64
#define NODE  128
#define EDGE  256
#define CNN   512
#define GT    (4*NODE)     // 512
#define GN    (4*EDGE)     // 1024
#define CONC  (NODE+CNN+EDGE) // 896
#define NBLK  389

typedef unsigned long long ULL;

#define PK(d,s)   asm("mov.b64 %0, {%1, %1};" : "=l"(d) : "f"(s))
#define UPK(lo,hi,p) asm("mov.b64 {%0, %1}, %2;" : "=f"(lo), "=f"(hi) : "l"(p))
#define FMA2(c,a,b) asm("fma.rn.f32x2 %0, %1, %2, %0;" : "+l"(c) : "l"(a), "l"(b))

__device__ __forceinline__ uint32_t smem_u32(const void* p){
    uint32_t a; asm("{ .reg .u64 t; cvta.to.shared.u64 t, %1; cvt.u32.u64 %0, t; }" : "=r"(a) : "l"(p)); return a;
}
#define LDMX4(r0,r1,r2,r3,addr) \
    asm volatile("ldmatrix.sync.aligned.m8n8.x4.shared.b16 {%0,%1,%2,%3}, [%4];" \
        : "=r"(r0), "=r"(r1), "=r"(r2), "=r"(r3) : "r"(addr))
#define MMA16816(c,a0,a1,a2,a3,b0,b1) \
    asm volatile("mma.sync.aligned.m16n8k16.row.col.f32.bf16.bf16.f32 " \
        "{%0,%1,%2,%3}, {%4,%5,%6,%7}, {%8,%9}, {%0,%1,%2,%3};" \
        : "+f"((c)[0]), "+f"((c)[1]), "+f"((c)[2]), "+f"((c)[3]) \
        : "r"(a0), "r"(a1), "r"(a2), "r"(a3), "r"(b0), "r"(b1))
#define CPA16(dst,src) \
    asm volatile("cp.async.cg.shared.global [%0], [%1], 16;" :: "r"(dst), "l"(src))
#define CPA8(dst,src) \
    asm volatile("cp.async.ca.shared.global [%0], [%1], 8;" :: "r"(dst), "l"(src))
#define CPA4(dst,src) \
    asm volatile("cp.async.ca.shared.global [%0], [%1], 4;" :: "r"(dst), "l"(src))
#define CPCOMMIT() asm volatile("cp.async.commit_group;")
#define CPWAIT(n)  asm volatile("cp.async.wait_group %0;" :: "n"(n))

// ---------------- persistent device state ----------------
__device__ float d_thtT[2][NODE*NN];
__device__ float d_thtNM[NN*NODE];
__device__ float d_tct[NN*NODE];
__device__ __nv_bfloat16 d_nhHi[2][MM*EDGE];
__device__ __nv_bfloat16 d_nhLo[2][MM*EDGE];
__device__ float d_nct[MM*EDGE];
__device__ float d_Ht[NN*EDGE];
__device__ float d_HtaP[2][NN*EDGE];
__device__ float d_cabs[NN*2], d_crel[NN*2];
__device__ float d_cstepP[2][NN*2];
__device__ int   d_flag;
__device__ int   d_mnt;
// half-split completion counters per rowTile
__device__ int   d_rowCntA[TSTEPS][24];   // colTiles 0..7  (k 0..127)
__device__ int   d_rowCntB[TSTEPS][24];   // colTiles 8..15 (k 128..255)
__device__ int   d_tgtCnt[TSTEPS];
__device__ int   d_epiCnt[TSTEPS];
__device__ int   d_gateTt[TSTEPS];
__device__ int   d_gateNt[TSTEPS];
__device__ float d_currNt[TSTEPS];
// weights
__device__ __nv_bfloat16 d_WNHi[GN*EDGE];
__device__ __nv_bfloat16 d_WNLo[GN*EDGE];
__device__ float d_WhhTT[NODE*GT];
__device__ float d_WxN[GN*2], d_bN[GN];
__device__ float d_WxT[GT*2], d_bT[GT];
__device__ float d_imgpart[NN*2];

__device__ __forceinline__ float sigm(float x){ return 1.f/(1.f+expf(-x)); }
__device__ __forceinline__ void wait_ge(volatile int* p, int v){
    while(*p < v){ __nanosleep(64); }
}

// dynamic smem layout
#define OFF_AHI 0
#define OFF_ALO 10240
#define OFF_BHI 20480
#define OFF_BLO 25600
#define BUF     30720
#define OFF_EPN 61440
#define OFF_EPS 69632
#define OFF_EPH 70656
#define OFF_W   71168
#define DSMEM_TOTAL 71680

// ---------------- init kernels ----------------
__global__ void k_zero(){
    long i0 = (long)blockIdx.x*blockDim.x + threadIdx.x;
    long st = (long)gridDim.x*blockDim.x;
    uint32_t* hh = (uint32_t*)&d_nhHi[0][0];
    uint32_t* hl = (uint32_t*)&d_nhLo[0][0];
    for(long i=i0;i<(long)MM*EDGE;i+=st){ hh[i]=0u; hl[i]=0u; }
    for(long i=i0;i<(long)MM*EDGE;i+=st) d_nct[i]=0.f;
    float* th = &d_thtT[0][0];
    for(long i=i0;i<2L*NN*NODE;i+=st) th[i]=0.f;
    for(long i=i0;i<(long)NN*NODE;i+=st){ d_tct[i]=0.f; d_thtNM[i]=0.f; }
    for(long i=i0;i<(long)NN*EDGE;i+=st){ d_Ht[i]=0.f; d_HtaP[0][i]=0.f; d_HtaP[1][i]=0.f; }
    if(i0<NN*2){ d_cabs[i0]=0.f; d_crel[i0]=0.f; d_cstepP[0][i0]=0.f; d_cstepP[1][i0]=0.f; }
    for(long i=i0;i<TSTEPS*24;i+=st){ ((int*)d_rowCntA)[i]=0; ((int*)d_rowCntB)[i]=0; }
    for(long i=i0;i<TSTEPS;i+=st){ d_tgtCnt[i]=0; d_epiCnt[i]=0; }
    if(i0==0){ d_flag=0; d_mnt=0; }
}

__global__ void k_tables(const int* __restrict__ thist, const int* __restrict__ nhist){
    int t = blockIdx.x + 1;
    int tid = threadIdx.x;
    __shared__ int s_cnt[256];
    __shared__ int s_any[256];
    int cnt=0, any=0;
    if(t < TOBS){
        for(int m=tid;m<MM;m+=256) cnt += (nhist[m] > (TOBS - t)) ? 1 : 0;
        for(int n=tid;n<NN;n+=256) any |= (thist[n] > (TOBS - t)) ? 1 : 0;
    }else{
        cnt = (tid==0)?MM:0; any = 1;
    }
    s_cnt[tid]=cnt; s_any[tid]=any;
    __syncthreads();
    for(int o=128;o>0;o>>=1){
        if(tid<o){ s_cnt[tid]+=s_cnt[tid+o]; s_any[tid]|=s_any[tid+o]; }
        __syncthreads();
    }
    if(tid==0){
        int gt = s_any[0]?1:0;
        int cn = s_cnt[0];
        d_gateTt[t]=gt; d_gateNt[t]=(gt && cn>0)?1:0; d_currNt[t]=(float)cn;
    }
}

__global__ void k_prep(const float* __restrict__ Whh_n, const float* __restrict__ Wih_n,
                       const float* __restrict__ bih_n, const float* __restrict__ bhh_n,
                       const float* __restrict__ Whh_t, const float* __restrict__ Wih_t,
                       const float* __restrict__ bih_t, const float* __restrict__ bhh_t,
                       const float* __restrict__ W_disp, const float* __restrict__ b_disp,
                       const float* __restrict__ img, const float* __restrict__ W_pred){
    int i0 = blockIdx.x*blockDim.x + threadIdx.x;
    int st = gridDim.x*blockDim.x;
    for(int i=i0;i<GN*EDGE;i+=st){
        int g=i/EDGE, k=i%EDGE; int e=g>>2, q=g&3;
        float v = Whh_n[(q*EDGE+e)*EDGE + k];
        __nv_bfloat16 hi = __float2bfloat16(v);
        d_WNHi[i] = hi;
        d_WNLo[i] = __float2bfloat16(v - __bfloat162float(hi));
    }
    for(int i=i0;i<NODE*GT;i+=st){
        int k=i/GT, g=i%GT; int e=g>>2, q=g&3;
        d_WhhTT[i] = Whh_t[(q*NODE+e)*NODE + k];
    }
    for(int r=i0;r<GN;r+=st){
        int e=r>>2, q=r&3; int o=q*EDGE+e;
        float w0=0.f,w1=0.f,bb=bih_n[o]+bhh_n[o];
        for(int d=0;d<EMB;d++){
            float wi=Wih_n[o*EMB+d];
            w0+=wi*W_disp[d*2]; w1+=wi*W_disp[d*2+1]; bb+=wi*b_disp[d];
        }
        d_WxN[r*2]=w0; d_WxN[r*2+1]=w1; d_bN[r]=bb;
    }
    for(int r=i0;r<GT;r+=st){
        int e=r>>2, q=r&3; int o=q*NODE+e;
        float w0=0.f,w1=0.f,bb=bih_t[o]+bhh_t[o];
        for(int d=0;d<EMB;d++){
            float wi=Wih_t[o*EMB+d];
            w0+=wi*W_disp[d*2]; w1+=wi*W_disp[d*2+1]; bb+=wi*b_disp[d];
        }
        d_WxT[r*2]=w0; d_WxT[r*2+1]=w1; d_bT[r]=bb;
    }
    for(int i=i0;i<NN*2;i+=st){
        int n=i>>1, j=i&1; float s=0.f;
        for(int c=0;c<CNN;c++) s += img[n*CNN+c]*W_pred[j*CONC + NODE + c];
        d_imgpart[i]=s;
    }
}

__device__ __forceinline__ void prefetch_chunk(uint32_t uS, uint32_t bo,
    const __nv_bfloat16* __restrict__ hHi, const __nv_bfloat16* __restrict__ hLo,
    int m0, int g0, int k0, int tid)
{
    #pragma unroll
    for(int g=0;g<2;g++){
        int j = tid + g*256;
        int row = j>>2, c16 = j&3;
        uint32_t d = bo + (uint32_t)(row*80 + c16*16);
        long soff = (long)(m0+row)*EDGE + k0 + c16*8;
        CPA16(uS + OFF_AHI + d, hHi + soff);
        CPA16(uS + OFF_ALO + d, hLo + soff);
    }
    {
        int row = tid>>2, c16 = tid&3;
        uint32_t d = bo + (uint32_t)(row*80 + c16*16);
        long soff = (long)(g0+row)*EDGE + k0 + c16*8;
        CPA16(uS + OFF_BHI + d, d_WNHi + soff);
        CPA16(uS + OFF_BLO + d, d_WNLo + soff);
    }
    CPCOMMIT();
}

__device__ __forceinline__ void prefetch_ep(uint32_t uS,
    const float* __restrict__ nstep_in, const int* __restrict__ nhist,
    int m0, int e0c, int tc, int tid)
{
    #pragma unroll
    for(int g=0;g<2;g++){
        int idx = tid + g*256;
        int row = idx>>2, q = idx&3;
        CPA16(uS + OFF_EPN + (uint32_t)(row*64 + q*16),
              &d_nct[(long)(m0+row)*EDGE + e0c + q*4]);
    }
    if(tid < 128){
        CPA8(uS + OFF_EPS + (uint32_t)(tid*8), &nstep_in[((m0+tid)*TOBS+tc)*2]);
        CPA4(uS + OFF_EPH + (uint32_t)(tid*4), &nhist[m0+tid]);
    }
}

// per-block attention weights for this tile's rows -> s_w[128]
__device__ void compute_w(float* s_w, int m0, int t, bool obs, int tc,
    const float* __restrict__ trel, const float* __restrict__ tabs,
    const float* __restrict__ nabs_in, const int* __restrict__ nhist,
    const float* __restrict__ W_att_t, const float* __restrict__ b_att_t,
    const float* __restrict__ W_att_n, const float* __restrict__ b_att_n,
    int wid, int lane)
{
    if(wid >= 4) return;
    int n = m0/KK + wid;
    if(n >= NN || n*KK >= m0+128) return;
    float currNf = d_currNt[t];
    float crel0,crel1,cab0,cab1;
    if(obs){
        int o2 = (n*TOBS+t)*2;
        crel0=trel[o2]; crel1=trel[o2+1];
        cab0 =tabs[o2]; cab1 =tabs[o2+1];
    }else{
        crel0=d_crel[n*2]; crel1=d_crel[n*2+1];
        cab0 =d_cabs[n*2]; cab1 =d_cabs[n*2+1];
    }
    float p0=0.f,p1=0.f,p2=0.f;
    #pragma unroll
    for(int a=lane;a<64;a+=32){
        float atv = W_att_t[a*2]*crel0 + W_att_t[a*2+1]*crel1 + b_att_t[a];
        p0 += atv*W_att_n[a*2];
        p1 += atv*W_att_n[a*2+1];
        p2 += atv*b_att_n[a];
    }
    #pragma unroll
    for(int o=1;o<32;o<<=1){
        p0 += __shfl_xor_sync(0xffffffffu,p0,o);
        p1 += __shfl_xor_sync(0xffffffffu,p1,o);
        p2 += __shfl_xor_sync(0xffffffffu,p2,o);
    }
    int m1 = n*KK + lane;
    int off1 = (m1*TOBS+tc)*2;
    float dx1 = nabs_in[off1]-cab0, dy1 = nabs_in[off1+1]-cab1;
    float mv1 = obs ? ((nhist[m1] > (TOBS - t)) ? 1.f : 0.f) : 1.f;
    float s0v = (dx1*p0+dy1*p1+p2)*currNf*0.125f*mv1;
    float s1v = -1e30f, mv2 = 0.f; int m2 = 0;
    if(lane < 16){
        m2 = n*KK + 32 + lane;
        int off2 = (m2*TOBS+tc)*2;
        float dx2 = nabs_in[off2]-cab0, dy2 = nabs_in[off2+1]-cab1;
        mv2 = obs ? ((nhist[m2] > (TOBS - t)) ? 1.f : 0.f) : 1.f;
        s1v = (dx2*p0+dy2*p1+p2)*currNf*0.125f*mv2;
    }
    float mx = fmaxf(s0v, s1v);
    #pragma unroll
    for(int o=1;o<32;o<<=1) mx = fmaxf(mx, __shfl_xor_sync(0xffffffffu,mx,o));
    float e0v = expf(s0v-mx)*mv1;
    float e1v = (lane<16) ? expf(s1v-mx)*mv2 : 0.f;
    float dn = e0v + e1v;
    #pragma unroll
    for(int o=1;o<32;o<<=1) dn += __shfl_xor_sync(0xffffffffu,dn,o);
    dn += 1e-6f;
    int r1 = m1 - m0;
    if(r1>=0 && r1<128) s_w[r1] = e0v/dn;
    if(lane<16){
        int r2 = m2 - m0;
        if(r2>=0 && r2<128) s_w[r2] = e1v/dn;
    }
}

// =========================================================================
__global__ void __launch_bounds__(256,3) k_run(
    const float* __restrict__ tabs, const float* __restrict__ trel, const float* __restrict__ tstep,
    const float* __restrict__ nabs_in, const float* __restrict__ nstep_in,
    const int* __restrict__ thist, const int* __restrict__ nhist,
    const float* __restrict__ W_att_t, const float* __restrict__ b_att_t,
    const float* __restrict__ W_att_n, const float* __restrict__ b_att_n,
    const float* __restrict__ W_pred, const float* __restrict__ b_pred,
    float* __restrict__ out)
{
    extern __shared__ __align__(128) char dsm[];
    const int bx = blockIdx.x;
    const int tid = threadIdx.x;

    const int bi = bx-1;
    const int rowTile = (bi>=0) ? (bi % 24) : 0;
    const int colTile = (bi>=0) ? (bi / 24) : 0;
    const int m0 = rowTile*128, g0 = colTile*64, e0c = colTile*16;
    const int wid = tid>>5, lane = tid&31;
    const int tig = lane&3, gid = lane>>2;
    const int wm = wid&3, wn = wid>>2;
    const uint32_t uS = smem_u32(dsm);
    const uint32_t aHiO = OFF_AHI + (uint32_t)((wm*32 + (lane&15))*80) + (uint32_t)((lane>>4)*16);
    const uint32_t aLoO = OFF_ALO + (uint32_t)((wm*32 + (lane&15))*80) + (uint32_t)((lane>>4)*16);
    const uint32_t bHiO = OFF_BHI + (uint32_t)((wn*32 + (lane&15))*80) + (uint32_t)((lane>>4)*16);
    const uint32_t bLoO = OFF_BLO + (uint32_t)((wn*32 + (lane&15))*80) + (uint32_t)((lane>>4)*16);
    float* sC  = (float*)dsm;
    float* sWh = (float*)(dsm + 34816);
    float* s_w = (float*)(dsm + OFF_W);

    for(int t=1; t<TSTEPS; t++){
        const int cur=(t-1)&1, nxt=t&1;
        const bool obs = (t < TOBS);
        const int tc = obs ? t : (TOBS-1);

        if(bx == 0){
            __shared__ float s_pred[NN*2];
            if(!obs){
                if(tid==0){
                    wait_ge(&d_epiCnt[t-1], 384);
                    wait_ge(&d_tgtCnt[t-1], 4);
                }
                __syncthreads();
                __threadfence();
                {
                    int gp = d_gateNt[t-1];
                    float4* Ht4 = (float4*)d_Ht;
                    float4* Ha4 = (float4*)d_HtaP[(t-1)&1];
                    for(int i=tid;i<NN*EDGE/4;i+=256){
                        if(gp) Ht4[i]=Ha4[i];
                        Ha4[i]=make_float4(0.f,0.f,0.f,0.f);
                    }
                }
                __threadfence();
                __syncthreads();
                if(tid==0) atomicExch(&d_mnt, t-1);
                {
                    int item = tid>>1, sub = tid&1;
                    int n = item>>1, j = item&1;
                    const float4* th4 = (const float4*)&d_thtNM[n*NODE + sub*64];
                    const float4* wp1 = (const float4*)&W_pred[j*CONC + sub*64];
                    float acc = 0.f;
                    #pragma unroll
                    for(int i=0;i<16;i++){
                        float4 a=th4[i], b=wp1[i];
                        acc += a.x*b.x + a.y*b.y + a.z*b.z + a.w*b.w;
                    }
                    const float4* hh4 = (const float4*)&d_Ht[n*EDGE + sub*128];
                    const float4* wp3 = (const float4*)&W_pred[j*CONC + NODE+CNN + sub*128];
                    #pragma unroll
                    for(int i=0;i<32;i++){
                        float4 a=hh4[i], b=wp3[i];
                        acc += a.x*b.x + a.y*b.y + a.z*b.z + a.w*b.w;
                    }
                    acc += __shfl_xor_sync(0xffffffffu, acc, 1);
                    if(sub==0) s_pred[item] = acc + d_imgpart[item] + b_pred[j];
                }
                __syncthreads();
                if(tid<NN*2){
                    float p=s_pred[tid];
                    d_cabs[tid]+=p;
                    float cr=d_crel[tid]+p; d_crel[tid]=cr;
                    d_cstepP[t&1][tid]=p;
                    int n=tid>>1, j=tid&1;
                    out[(n*PREDN + (t-TOBS))*2 + j] = cr;
                }
                __threadfence();
                __syncthreads();
                if(tid==0) atomicExch(&d_flag, t);
            }else{
                if(t==TOBS-1 && tid<NN*2){
                    int n=tid>>1, j=tid&1; int off=(n*TOBS+t)*2+j;
                    d_cabs[tid]=tabs[off]; d_crel[tid]=trel[off];
                }
                if(t>=2){
                    if(tid==0) wait_ge(&d_epiCnt[t-1], 384);
                    __syncthreads();
                    __threadfence();
                    int gp = d_gateNt[t-1];
                    float4* Ht4 = (float4*)d_Ht;
                    float4* Ha4 = (float4*)d_HtaP[(t-1)&1];
                    for(int i=tid;i<NN*EDGE/4;i+=256){
                        if(gp) Ht4[i]=Ha4[i];
                        Ha4[i]=make_float4(0.f,0.f,0.f,0.f);
                    }
                    __threadfence();
                    __syncthreads();
                    if(tid==0) atomicExch(&d_mnt, t-1);
                }
            }
        }
        else if(bx <= 384){
            int gate_n = d_gateNt[t];
            if(!gate_n){
                int row = tid>>1, half = tid&1;
                long base = (long)(m0+row)*EDGE + e0c + half*8;
                *(uint4*)&d_nhHi[nxt][base] = *(const uint4*)&d_nhHi[cur][base];
                *(uint4*)&d_nhLo[nxt][base] = *(const uint4*)&d_nhLo[cur][base];
                __threadfence();
                __syncthreads();
                if(tid==0){
                    if(colTile<8) atomicAdd(&d_rowCntA[t][rowTile], 1);
                    else          atomicAdd(&d_rowCntB[t][rowTile], 1);
                    atomicAdd(&d_epiCnt[t], 1);
                }
                continue;
            }
            const __nv_bfloat16* hHi = d_nhHi[cur];
            const __nv_bfloat16* hLo = d_nhLo[cur];
            float C[2][4][4];
            #pragma unroll
            for(int mi=0;mi<2;mi++)
                #pragma unroll
                for(int j=0;j<4;j++){ C[mi][j][0]=0.f; C[mi][j][1]=0.f; C[mi][j][2]=0.f; C[mi][j][3]=0.f; }

            // self-written data: prefetch before any producer wait
            prefetch_ep(uS, nstep_in, nhist, m0, e0c, tc, tid);
            // gate chunks 0-3 on first half of producers only
            if(t>=2){
                if(tid==0) wait_ge(&d_rowCntA[t-1][rowTile], 8);
                __syncthreads();
                __threadfence();
            }
            prefetch_chunk(uS, 0u, hHi, hLo, m0, g0, 0, tid);
            if(obs)
                compute_w(s_w, m0, t, true, tc, trel, tabs, nabs_in, nhist,
                          W_att_t, b_att_t, W_att_n, b_att_n, wid, lane);
            #pragma unroll
            for(int ch=0; ch<8; ch++){
                uint32_t bo = (ch&1)*BUF;
                if(ch<7){
                    if(ch==3 && t>=2){
                        // chunks 4-7 read colTiles 8..15 of step t-1
                        if(tid==0) wait_ge(&d_rowCntB[t-1][rowTile], 8);
                        __syncthreads();
                        __threadfence();
                    }
                    prefetch_chunk(uS, ((ch+1)&1)*BUF, hHi, hLo, m0, g0, (ch+1)*32, tid);
                    CPWAIT(1);
                }else{
                    CPWAIT(0);
                }
                __syncthreads();
                #pragma unroll
                for(int ktl=0; ktl<2; ktl++){
                    uint32_t koff = bo + ktl*32;
                    uint32_t ah[2][4], al[2][4];
                    #pragma unroll
                    for(int mi=0;mi<2;mi++){
                        LDMX4(ah[mi][0],ah[mi][1],ah[mi][2],ah[mi][3], uS + aHiO + (uint32_t)(mi*16*80) + koff);
                        LDMX4(al[mi][0],al[mi][1],al[mi][2],al[mi][3], uS + aLoO + (uint32_t)(mi*16*80) + koff);
                    }
                    #pragma unroll
                    for(int ng=0; ng<2; ng++){
                        uint32_t bh0,bh1,bh2,bh3, bl0,bl1,bl2,bl3;
                        LDMX4(bh0,bh1,bh2,bh3, uS + bHiO + (uint32_t)(ng*16*80) + koff);
                        LDMX4(bl0,bl1,bl2,bl3, uS + bLoO + (uint32_t)(ng*16*80) + koff);
                        MMA16816(C[0][ng*2],   ah[0][0],ah[0][1],ah[0][2],ah[0][3], bh0,bh2);
                        MMA16816(C[0][ng*2+1], ah[0][0],ah[0][1],ah[0][2],ah[0][3], bh1,bh3);
                        MMA16816(C[1][ng*2],   ah[1][0],ah[1][1],ah[1][2],ah[1][3], bh0,bh2);
                        MMA16816(C[1][ng*2+1], ah[1][0],ah[1][1],ah[1][2],ah[1][3], bh1,bh3);
                        MMA16816(C[0][ng*2],   ah[0][0],ah[0][1],ah[0][2],ah[0][3], bl0,bl2);
                        MMA16816(C[0][ng*2+1], ah[0][0],ah[0][1],ah[0][2],ah[0][3], bl1,bl3);
                        MMA16816(C[1][ng*2],   ah[1][0],ah[1][1],ah[1][2],ah[1][3], bl0,bl2);
                        MMA16816(C[1][ng*2+1], ah[1][0],ah[1][1],ah[1][2],ah[1][3], bl1,bl3);
                        MMA16816(C[0][ng*2],   al[0][0],al[0][1],al[0][2],al[0][3], bh0,bh2);
                        MMA16816(C[0][ng*2+1], al[0][0],al[0][1],al[0][2],al[0][3], bh1,bh3);
                        MMA16816(C[1][ng*2],   al[1][0],al[1][1],al[1][2],al[1][3], bh0,bh2);
                        MMA16816(C[1][ng*2+1], al[1][0],al[1][1],al[1][2],al[1][3], bh1,bh3);
                    }
                }
                __syncthreads();
            }

            #pragma unroll
            for(int mi=0;mi<2;mi++){
                int r0 = wm*32 + mi*16 + gid;
                #pragma unroll
                for(int jj=0;jj<4;jj++){
                    int col = wn*32 + jj*8 + tig*2;
                    *(float2*)&sC[r0*68+col]     = make_float2(C[mi][jj][0],C[mi][jj][1]);
                    *(float2*)&sC[(r0+8)*68+col] = make_float2(C[mi][jj][2],C[mi][jj][3]);
                }
            }
            if(!obs){
                if(tid==0) wait_ge(&d_flag, t);
                __syncthreads();
                __threadfence();
                compute_w(s_w, m0, t, false, tc, trel, tabs, nabs_in, nhist,
                          W_att_t, b_att_t, W_att_n, b_att_n, wid, lane);
            }
            if(tid==0 && t>=3) wait_ge(&d_mnt, t-2);
            __syncthreads();
            __threadfence();

            {
                int row = tid>>1, half = tid&1;
                int m = m0 + row;
                long base = (long)m*EDGE + e0c + half*8;
                float2 xv = *(const float2*)(dsm + OFF_EPS + row*8);
                int hist = *(const int*)(dsm + OFF_EPH + row*4);
                bool mv = obs ? (hist > (TOBS - t)) : true;
                bool un = mv;
                float wv = s_w[row];
                const float* sn = (const float*)(dsm + OFF_EPN + row*64 + half*32);
                float coldA[8];
                #pragma unroll
                for(int cc=0;cc<8;cc++) coldA[cc]=sn[cc];
                const float* g4p = &sC[row*68 + half*32];
                float hnew[8], cnew[8];
                #pragma unroll
                for(int cc=0;cc<8;cc++){
                    int gb = g0 + half*32 + cc*4;
                    float4 wA = *(const float4*)&d_WxN[gb*2];
                    float4 wB = *(const float4*)&d_WxN[gb*2+4];
                    float4 bb = *(const float4*)&d_bN[gb];
                    float gi_ = g4p[4*cc+0] + xv.x*wA.x + xv.y*wA.y + bb.x;
                    float gf  = g4p[4*cc+1] + xv.x*wA.z + xv.y*wA.w + bb.y;
                    float gg  = g4p[4*cc+2] + xv.x*wB.x + xv.y*wB.y + bb.z;
                    float go  = g4p[4*cc+3] + xv.x*wB.z + xv.y*wB.w + bb.w;
                    float c2 = sigm(gf)*coldA[cc] + sigm(gi_)*tanhf(gg);
                    hnew[cc] = sigm(go)*tanhf(c2);
                    cnew[cc] = un ? c2 : coldA[cc];
                }
                __align__(16) __nv_bfloat16 hb[8], lb[8];
                if(un){
                    #pragma unroll
                    for(int cc=0;cc<8;cc++){
                        hb[cc] = __float2bfloat16(hnew[cc]);
                        lb[cc] = __float2bfloat16(hnew[cc] - __bfloat162float(hb[cc]));
                    }
                }else{
                    *(uint4*)hb = *(const uint4*)&hHi[base];
                    *(uint4*)lb = *(const uint4*)&hLo[base];
                    #pragma unroll
                    for(int cc=0;cc<8;cc++)
                        hnew[cc] = __bfloat162float(hb[cc]) + __bfloat162float(lb[cc]);
                }
                *(uint4*)&d_nhHi[nxt][base] = *(uint4*)hb;
                *(uint4*)&d_nhLo[nxt][base] = *(uint4*)lb;
                *(float4*)&d_nct[base]   = make_float4(cnew[0],cnew[1],cnew[2],cnew[3]);
                *(float4*)&d_nct[base+4] = make_float4(cnew[4],cnew[5],cnew[6],cnew[7]);
                float* wout = &sWh[row*16 + half*8];
                *(float4*)&wout[0] = make_float4(wv*hnew[0],wv*hnew[1],wv*hnew[2],wv*hnew[3]);
                *(float4*)&wout[4] = make_float4(wv*hnew[4],wv*hnew[5],wv*hnew[6],wv*hnew[7]);
            }
            __syncthreads();
            if(tid < 64){
                int gi = tid>>4, col = tid&15;
                int n = m0/KK + gi;
                int lo = n*KK - m0; if(lo<0) lo=0;
                int hi2 = n*KK + KK - m0; if(hi2>128) hi2=128;
                if(lo < hi2 && n < NN){
                    float s=0.f;
                    for(int r=lo;r<hi2;r++) s += sWh[r*16+col];
                    atomicAdd(&d_HtaP[t&1][n*EDGE + e0c + col], s);
                }
            }
            __threadfence();
            __syncthreads();
            if(tid==0){
                if(colTile<8) atomicAdd(&d_rowCntA[t][rowTile], 1);
                else          atomicAdd(&d_rowCntB[t][rowTile], 1);
                atomicAdd(&d_epiCnt[t], 1);
            }
        }
        else{
            if(t>=2){
                if(tid==0) wait_ge(&d_tgtCnt[t-1], 4);
                __syncthreads();
                __threadfence();
            }
            int bj = bx - 385;
            int gate_t = d_gateTt[t];
            if(!gate_t){
                int e0 = bj*32;
                for(int i=tid;i<32*NN;i+=256){
                    int e = e0 + (i>>6), n = i&63;
                    d_thtT[nxt][e*NN+n] = d_thtT[cur][e*NN+n];
                }
                __threadfence();
                __syncthreads();
                if(tid==0) atomicAdd(&d_tgtCnt[t], 1);
                continue;
            }
            float (*As)[68]  = (float(*)[68]) (dsm);
            float (*Bs)[140] = (float(*)[140])(dsm + sizeof(float)*32*68);
            int g0t = bj*128, e0 = bj*32;
            const float* A = d_thtT[cur];
            int ty = tid>>4, tx = tid&15;
            int pb = tx*8; pb += (pb>>5)<<2;
            ULL accp[4][4];
            #pragma unroll
            for(int i=0;i<4;i++){
                #pragma unroll
                for(int j=0;j<4;j++) accp[i][j]=0ull;
            }
            for(int kt=0; kt<NODE; kt+=32){
                #pragma unroll
                for(int g=0;g<2;g++){
                    int idx = tid + g*256;
                    int k = idx>>4, nq = (idx&15)*4;
                    *(float4*)&As[k][nq] = *(const float4*)&A[(kt+k)*NN + nq];
                }
                #pragma unroll
                for(int g=0;g<4;g++){
                    int idx = tid + g*256;
                    int k = idx>>5, cq = (idx&31)*4;
                    int pc = cq + ((cq>>5)<<2);
                    *(float4*)&Bs[k][pc] = *(const float4*)&d_WhhTT[(kt+k)*GT + g0t+cq];
                }
                __syncthreads();
                #pragma unroll
                for(int k=0;k<32;k++){
                    float4 a0 = *(const float4*)&As[k][ty*4];
                    ulonglong2 bb0 = *(const ulonglong2*)&Bs[k][pb];
                    ulonglong2 bb1 = *(const ulonglong2*)&Bs[k][pb+4];
                    ULL ap;
                    PK(ap,a0.x); FMA2(accp[0][0],ap,bb0.x); FMA2(accp[0][1],ap,bb0.y); FMA2(accp[0][2],ap,bb1.x); FMA2(accp[0][3],ap,bb1.y);
                    PK(ap,a0.y); FMA2(accp[1][0],ap,bb0.x); FMA2(accp[1][1],ap,bb0.y); FMA2(accp[1][2],ap,bb1.x); FMA2(accp[1][3],ap,bb1.y);
                    PK(ap,a0.z); FMA2(accp[2][0],ap,bb0.x); FMA2(accp[2][1],ap,bb0.y); FMA2(accp[2][2],ap,bb1.x); FMA2(accp[2][3],ap,bb1.y);
                    PK(ap,a0.w); FMA2(accp[3][0],ap,bb0.x); FMA2(accp[3][1],ap,bb0.y); FMA2(accp[3][2],ap,bb1.x); FMA2(accp[3][3],ap,bb1.y);
                }
                __syncthreads();
            }
            if(!obs){
                if(tid==0){ wait_ge(&d_flag, t); }
                __syncthreads();
                __threadfence();
            }
            #pragma unroll
            for(int i=0;i<4;i++){
                int n = ty*4 + i;
                float x0, x1;
                if(obs){ int o2=(n*TOBS+t)*2; x0=tstep[o2]; x1=tstep[o2+1]; }
                else   { x0=d_cstepP[t&1][n*2]; x1=d_cstepP[t&1][n*2+1]; }
                bool tm = obs ? (thist[n] > (TOBS - t)) : true;
                #pragma unroll
                for(int c=0;c<2;c++){
                    float g4[4];
                    UPK(g4[0],g4[1],accp[i][c*2]);
                    UPK(g4[2],g4[3],accp[i][c*2+1]);
                    int rr = g0t + tx*8 + c*4;
                    #pragma unroll
                    for(int q=0;q<4;q++)
                        g4[q] += x0*d_WxT[(rr+q)*2] + x1*d_WxT[(rr+q)*2+1] + d_bT[rr+q];
                    float ig=sigm(g4[0]), fg=sigm(g4[1]), gg=tanhf(g4[2]), og=sigm(g4[3]);
                    int e = e0 + tx*2 + c;
                    float cold = d_tct[n*NODE+e];
                    float c2 = fg*cold + ig*gg;
                    float h2 = og*tanhf(c2);
                    bool un = tm;
                    float hv;
                    if(un){ d_tct[n*NODE+e]=c2; hv=h2; }
                    else  { hv = d_thtT[cur][e*NN+n]; }
                    d_thtT[nxt][e*NN+n]=hv;
                    d_thtNM[n*NODE+e]=hv;
                }
            }
            __threadfence();
            __syncthreads();
            if(tid==0) atomicAdd(&d_tgtCnt[t], 1);
        }
    }
}

// ---------------- launch ----------------
extern "C" void kernel_launch(void* const* d_in, const int* in_sizes, int n_in,
                              void* d_out, int out_size)
{
    const float* img    = (const float*)d_in[0];
    const float* tabs   = (const float*)d_in[1];
    const float* trel   = (const float*)d_in[2];
    const float* tstep  = (const float*)d_in[3];
    const float* nabs   = (const float*)d_in[4];
    const float* nstep  = (const float*)d_in[6];
    const int*   thist  = (const int*)d_in[7];
    const int*   nhist  = (const int*)d_in[8];
    const float* W_disp = (const float*)d_in[9];
    const float* b_disp = (const float*)d_in[10];
    const float* Wih_t  = (const float*)d_in[11];
    const float* Whh_t  = (const float*)d_in[12];
    const float* bih_t  = (const float*)d_in[13];
    const float* bhh_t  = (const float*)d_in[14];
    const float* Wih_n  = (const float*)d_in[15];
    const float* Whh_n  = (const float*)d_in[16];
    const float* bih_n  = (const float*)d_in[17];
    const float* bhh_n  = (const float*)d_in[18];
    const float* W_att_t= (const float*)d_in[19];
    const float* b_att_t= (const float*)d_in[20];
    const float* W_att_n= (const float*)d_in[21];
    const float* b_att_n= (const float*)d_in[22];
    const float* W_pred = (const float*)d_in[23];
    const float* b_pred = (const float*)d_in[24];
    float* out = (float*)d_out;

    static int s_attr_done = 0;
    if(!s_attr_done){
        cudaFuncSetAttribute(k_run, cudaFuncAttributeMaxDynamicSharedMemorySize, DSMEM_TOTAL);
        s_attr_done = 1;
    }

    k_zero<<<256,256>>>();
    k_tables<<<TSTEPS-1,256>>>(thist,nhist);
    k_prep<<<256,256>>>(Whh_n,Wih_n,bih_n,bhh_n,Whh_t,Wih_t,bih_t,bhh_t,
                        W_disp,b_disp,img,W_pred);
    k_run<<<NBLK,256,DSMEM_TOTAL>>>(tabs,trel,tstep,nabs,nstep,thist,nhist,
                        W_att_t,b_att_t,W_att_n,b_att_n,W_pred,b_pred,out);
}

// round 15
// speedup vs baseline: 1.2669x; 1.1227x over previous
#include <cuda_runtime.h>
#include <cuda_bf16.h>
#include <math.h>
#include <stdint.h>

#define NN    64
#define KK    48
#define MM    (NN*KK)      // 3072
#define TOBS  30
#define PREDN 15
#define TSTEPS (TOBS+PREDN)  // 45, t runs 1..44
#define EMB   64
#define NODE  128
#define EDGE  256
#define CNN   512
#define GT    (4*NODE)     // 512
#define GN    (4*EDGE)     // 1024
#define CONC  (NODE+CNN+EDGE) // 896
#define NBLK  389

typedef unsigned long long ULL;

#define PK(d,s)   asm("mov.b64 %0, {%1, %1};" : "=l"(d) : "f"(s))
#define UPK(lo,hi,p) asm("mov.b64 {%0, %1}, %2;" : "=f"(lo), "=f"(hi) : "l"(p))
#define FMA2(c,a,b) asm("fma.rn.f32x2 %0, %1, %2, %0;" : "+l"(c) : "l"(a), "l"(b))

__device__ __forceinline__ uint32_t smem_u32(const void* p){
    uint32_t a; asm("{ .reg .u64 t; cvta.to.shared.u64 t, %1; cvt.u32.u64 %0, t; }" : "=r"(a) : "l"(p)); return a;
}
#define LDMX4(r0,r1,r2,r3,addr) \
    asm volatile("ldmatrix.sync.aligned.m8n8.x4.shared.b16 {%0,%1,%2,%3}, [%4];" \
        : "=r"(r0), "=r"(r1), "=r"(r2), "=r"(r3) : "r"(addr))
#define MMA16816(c,a0,a1,a2,a3,b0,b1) \
    asm volatile("mma.sync.aligned.m16n8k16.row.col.f32.bf16.bf16.f32 " \
        "{%0,%1,%2,%3}, {%4,%5,%6,%7}, {%8,%9}, {%0,%1,%2,%3};" \
        : "+f"((c)[0]), "+f"((c)[1]), "+f"((c)[2]), "+f"((c)[3]) \
        : "r"(a0), "r"(a1), "r"(a2), "r"(a3), "r"(b0), "r"(b1))
#define CPA16(dst,src) \
    asm volatile("cp.async.cg.shared.global [%0], [%1], 16;" :: "r"(dst), "l"(src))
#define CPA8(dst,src) \
    asm volatile("cp.async.ca.shared.global [%0], [%1], 8;" :: "r"(dst), "l"(src))
#define CPA4(dst,src) \
    asm volatile("cp.async.ca.shared.global [%0], [%1], 4;" :: "r"(dst), "l"(src))
#define CPCOMMIT() asm volatile("cp.async.commit_group;")
#define CPWAIT(n)  asm volatile("cp.async.wait_group %0;" :: "n"(n))

// ---------------- persistent device state ----------------
__device__ float d_thtT[2][NODE*NN];
__device__ float d_thtNM[NN*NODE];
__device__ float d_tct[NN*NODE];
__device__ __nv_bfloat16 d_nh[2][MM*EDGE];   // nearby h, single bf16
__device__ float d_nct[MM*EDGE];
__device__ float d_Ht[NN*EDGE];
__device__ float d_HtaP[2][NN*EDGE];
__device__ float d_cabs[NN*2], d_crel[NN*2];
__device__ float d_cstepP[2][NN*2];
__device__ int   d_flag;
__device__ int   d_mnt;
// half-split completion counters per rowTile
__device__ int   d_rowCntA[TSTEPS][24];   // colTiles 0..7  (k 0..127)
__device__ int   d_rowCntB[TSTEPS][24];   // colTiles 8..15 (k 128..255)
__device__ int   d_tgtCnt[TSTEPS];
__device__ int   d_epiCnt[TSTEPS];
__device__ int   d_gateTt[TSTEPS];
__device__ int   d_gateNt[TSTEPS];
__device__ float d_currNt[TSTEPS];
// weights
__device__ __nv_bfloat16 d_WN[GN*EDGE];   // nearby Whh gate-interleaved [g][k], bf16
__device__ float d_WhhTT[NODE*GT];
__device__ float d_WxN[GN*2], d_bN[GN];
__device__ float d_WxT[GT*2], d_bT[GT];
__device__ float d_imgpart[NN*2];

__device__ __forceinline__ float sigm(float x){ return 1.f/(1.f+expf(-x)); }
__device__ __forceinline__ void wait_ge(volatile int* p, int v){
    while(*p < v){ __nanosleep(64); }
}

// dynamic smem layout
// mainloop: two BUF buffers (A 128x32 bf16 @80B rows = 10240; B 64x32 @80B = 5120)
// staging after mainloop: sC f32[128][68] @0 (34816), sWh @34816 (8192)
// ep region (disjoint from staging): 43008..53248
#define OFF_A   0
#define OFF_B   10240
#define BUF     15360
#define OFF_EPN 43008
#define OFF_EPS 51200
#define OFF_EPH 52224
#define OFF_W   52736
#define DSMEM_TOTAL 53248

// ---------------- init kernels ----------------
__global__ void k_zero(){
    long i0 = (long)blockIdx.x*blockDim.x + threadIdx.x;
    long st = (long)gridDim.x*blockDim.x;
    uint32_t* hh = (uint32_t*)&d_nh[0][0];
    for(long i=i0;i<(long)MM*EDGE;i+=st) hh[i]=0u;   // covers both parity bufs (2*MM*EDGE bf16)
    for(long i=i0;i<(long)MM*EDGE;i+=st) d_nct[i]=0.f;
    float* th = &d_thtT[0][0];
    for(long i=i0;i<2L*NN*NODE;i+=st) th[i]=0.f;
    for(long i=i0;i<(long)NN*NODE;i+=st){ d_tct[i]=0.f; d_thtNM[i]=0.f; }
    for(long i=i0;i<(long)NN*EDGE;i+=st){ d_Ht[i]=0.f; d_HtaP[0][i]=0.f; d_HtaP[1][i]=0.f; }
    if(i0<NN*2){ d_cabs[i0]=0.f; d_crel[i0]=0.f; d_cstepP[0][i0]=0.f; d_cstepP[1][i0]=0.f; }
    for(long i=i0;i<TSTEPS*24;i+=st){ ((int*)d_rowCntA)[i]=0; ((int*)d_rowCntB)[i]=0; }
    for(long i=i0;i<TSTEPS;i+=st){ d_tgtCnt[i]=0; d_epiCnt[i]=0; }
    if(i0==0){ d_flag=0; d_mnt=0; }
}

__global__ void k_tables(const int* __restrict__ thist, const int* __restrict__ nhist){
    int t = blockIdx.x + 1;
    int tid = threadIdx.x;
    __shared__ int s_cnt[256];
    __shared__ int s_any[256];
    int cnt=0, any=0;
    if(t < TOBS){
        for(int m=tid;m<MM;m+=256) cnt += (nhist[m] > (TOBS - t)) ? 1 : 0;
        for(int n=tid;n<NN;n+=256) any |= (thist[n] > (TOBS - t)) ? 1 : 0;
    }else{
        cnt = (tid==0)?MM:0; any = 1;
    }
    s_cnt[tid]=cnt; s_any[tid]=any;
    __syncthreads();
    for(int o=128;o>0;o>>=1){
        if(tid<o){ s_cnt[tid]+=s_cnt[tid+o]; s_any[tid]|=s_any[tid+o]; }
        __syncthreads();
    }
    if(tid==0){
        int gt = s_any[0]?1:0;
        int cn = s_cnt[0];
        d_gateTt[t]=gt; d_gateNt[t]=(gt && cn>0)?1:0; d_currNt[t]=(float)cn;
    }
}

__global__ void k_prep(const float* __restrict__ Whh_n, const float* __restrict__ Wih_n,
                       const float* __restrict__ bih_n, const float* __restrict__ bhh_n,
                       const float* __restrict__ Whh_t, const float* __restrict__ Wih_t,
                       const float* __restrict__ bih_t, const float* __restrict__ bhh_t,
                       const float* __restrict__ W_disp, const float* __restrict__ b_disp,
                       const float* __restrict__ img, const float* __restrict__ W_pred){
    int i0 = blockIdx.x*blockDim.x + threadIdx.x;
    int st = gridDim.x*blockDim.x;
    for(int i=i0;i<GN*EDGE;i+=st){
        int g=i/EDGE, k=i%EDGE; int e=g>>2, q=g&3;
        d_WN[i] = __float2bfloat16(Whh_n[(q*EDGE+e)*EDGE + k]);
    }
    for(int i=i0;i<NODE*GT;i+=st){
        int k=i/GT, g=i%GT; int e=g>>2, q=g&3;
        d_WhhTT[i] = Whh_t[(q*NODE+e)*NODE + k];
    }
    for(int r=i0;r<GN;r+=st){
        int e=r>>2, q=r&3; int o=q*EDGE+e;
        float w0=0.f,w1=0.f,bb=bih_n[o]+bhh_n[o];
        for(int d=0;d<EMB;d++){
            float wi=Wih_n[o*EMB+d];
            w0+=wi*W_disp[d*2]; w1+=wi*W_disp[d*2+1]; bb+=wi*b_disp[d];
        }
        d_WxN[r*2]=w0; d_WxN[r*2+1]=w1; d_bN[r]=bb;
    }
    for(int r=i0;r<GT;r+=st){
        int e=r>>2, q=r&3; int o=q*NODE+e;
        float w0=0.f,w1=0.f,bb=bih_t[o]+bhh_t[o];
        for(int d=0;d<EMB;d++){
            float wi=Wih_t[o*EMB+d];
            w0+=wi*W_disp[d*2]; w1+=wi*W_disp[d*2+1]; bb+=wi*b_disp[d];
        }
        d_WxT[r*2]=w0; d_WxT[r*2+1]=w1; d_bT[r]=bb;
    }
    for(int i=i0;i<NN*2;i+=st){
        int n=i>>1, j=i&1; float s=0.f;
        for(int c=0;c<CNN;c++) s += img[n*CNN+c]*W_pred[j*CONC + NODE + c];
        d_imgpart[i]=s;
    }
}

__device__ __forceinline__ void prefetch_chunk(uint32_t uS, uint32_t bo,
    const __nv_bfloat16* __restrict__ hN, int m0, int g0, int k0, int tid)
{
    #pragma unroll
    for(int g=0;g<2;g++){
        int j = tid + g*256;
        int row = j>>2, c16 = j&3;
        uint32_t d = bo + (uint32_t)(row*80 + c16*16);
        CPA16(uS + OFF_A + d, hN + (long)(m0+row)*EDGE + k0 + c16*8);
    }
    {
        int row = tid>>2, c16 = tid&3;
        uint32_t d = bo + (uint32_t)(row*80 + c16*16);
        CPA16(uS + OFF_B + d, d_WN + (long)(g0+row)*EDGE + k0 + c16*8);
    }
    CPCOMMIT();
}

__device__ __forceinline__ void prefetch_ep(uint32_t uS,
    const float* __restrict__ nstep_in, const int* __restrict__ nhist,
    int m0, int e0c, int tc, int tid)
{
    #pragma unroll
    for(int g=0;g<2;g++){
        int idx = tid + g*256;
        int row = idx>>2, q = idx&3;
        CPA16(uS + OFF_EPN + (uint32_t)(row*64 + q*16),
              &d_nct[(long)(m0+row)*EDGE + e0c + q*4]);
    }
    if(tid < 128){
        CPA8(uS + OFF_EPS + (uint32_t)(tid*8), &nstep_in[((m0+tid)*TOBS+tc)*2]);
        CPA4(uS + OFF_EPH + (uint32_t)(tid*4), &nhist[m0+tid]);
    }
}

// per-block attention weights for this tile's rows -> s_w[128]
__device__ void compute_w(float* s_w, int m0, int t, bool obs, int tc,
    const float* __restrict__ trel, const float* __restrict__ tabs,
    const float* __restrict__ nabs_in, const int* __restrict__ nhist,
    const float* __restrict__ W_att_t, const float* __restrict__ b_att_t,
    const float* __restrict__ W_att_n, const float* __restrict__ b_att_n,
    int wid, int lane)
{
    if(wid >= 4) return;
    int n = m0/KK + wid;
    if(n >= NN || n*KK >= m0+128) return;
    float currNf = d_currNt[t];
    float crel0,crel1,cab0,cab1;
    if(obs){
        int o2 = (n*TOBS+t)*2;
        crel0=trel[o2]; crel1=trel[o2+1];
        cab0 =tabs[o2]; cab1 =tabs[o2+1];
    }else{
        crel0=d_crel[n*2]; crel1=d_crel[n*2+1];
        cab0 =d_cabs[n*2]; cab1 =d_cabs[n*2+1];
    }
    float p0=0.f,p1=0.f,p2=0.f;
    #pragma unroll
    for(int a=lane;a<64;a+=32){
        float atv = W_att_t[a*2]*crel0 + W_att_t[a*2+1]*crel1 + b_att_t[a];
        p0 += atv*W_att_n[a*2];
        p1 += atv*W_att_n[a*2+1];
        p2 += atv*b_att_n[a];
    }
    #pragma unroll
    for(int o=1;o<32;o<<=1){
        p0 += __shfl_xor_sync(0xffffffffu,p0,o);
        p1 += __shfl_xor_sync(0xffffffffu,p1,o);
        p2 += __shfl_xor_sync(0xffffffffu,p2,o);
    }
    int m1 = n*KK + lane;
    int off1 = (m1*TOBS+tc)*2;
    float dx1 = nabs_in[off1]-cab0, dy1 = nabs_in[off1+1]-cab1;
    float mv1 = obs ? ((nhist[m1] > (TOBS - t)) ? 1.f : 0.f) : 1.f;
    float s0v = (dx1*p0+dy1*p1+p2)*currNf*0.125f*mv1;
    float s1v = -1e30f, mv2 = 0.f; int m2 = 0;
    if(lane < 16){
        m2 = n*KK + 32 + lane;
        int off2 = (m2*TOBS+tc)*2;
        float dx2 = nabs_in[off2]-cab0, dy2 = nabs_in[off2+1]-cab1;
        mv2 = obs ? ((nhist[m2] > (TOBS - t)) ? 1.f : 0.f) : 1.f;
        s1v = (dx2*p0+dy2*p1+p2)*currNf*0.125f*mv2;
    }
    float mx = fmaxf(s0v, s1v);
    #pragma unroll
    for(int o=1;o<32;o<<=1) mx = fmaxf(mx, __shfl_xor_sync(0xffffffffu,mx,o));
    float e0v = expf(s0v-mx)*mv1;
    float e1v = (lane<16) ? expf(s1v-mx)*mv2 : 0.f;
    float dn = e0v + e1v;
    #pragma unroll
    for(int o=1;o<32;o<<=1) dn += __shfl_xor_sync(0xffffffffu,dn,o);
    dn += 1e-6f;
    int r1 = m1 - m0;
    if(r1>=0 && r1<128) s_w[r1] = e0v/dn;
    if(lane<16){
        int r2 = m2 - m0;
        if(r2>=0 && r2<128) s_w[r2] = e1v/dn;
    }
}

// =========================================================================
__global__ void __launch_bounds__(256,3) k_run(
    const float* __restrict__ tabs, const float* __restrict__ trel, const float* __restrict__ tstep,
    const float* __restrict__ nabs_in, const float* __restrict__ nstep_in,
    const int* __restrict__ thist, const int* __restrict__ nhist,
    const float* __restrict__ W_att_t, const float* __restrict__ b_att_t,
    const float* __restrict__ W_att_n, const float* __restrict__ b_att_n,
    const float* __restrict__ W_pred, const float* __restrict__ b_pred,
    float* __restrict__ out)
{
    extern __shared__ __align__(128) char dsm[];
    const int bx = blockIdx.x;
    const int tid = threadIdx.x;

    const int bi = bx-1;
    const int rowTile = (bi>=0) ? (bi % 24) : 0;
    const int colTile = (bi>=0) ? (bi / 24) : 0;
    const int m0 = rowTile*128, g0 = colTile*64, e0c = colTile*16;
    const int wid = tid>>5, lane = tid&31;
    const int tig = lane&3, gid = lane>>2;
    const int wm = wid&3, wn = wid>>2;
    const uint32_t uS = smem_u32(dsm);
    const uint32_t aO = OFF_A + (uint32_t)((wm*32 + (lane&15))*80) + (uint32_t)((lane>>4)*16);
    const uint32_t bO = OFF_B + (uint32_t)((wn*32 + (lane&15))*80) + (uint32_t)((lane>>4)*16);
    float* sC  = (float*)dsm;
    float* sWh = (float*)(dsm + 34816);
    float* s_w = (float*)(dsm + OFF_W);

    for(int t=1; t<TSTEPS; t++){
        const int cur=(t-1)&1, nxt=t&1;
        const bool obs = (t < TOBS);
        const int tc = obs ? t : (TOBS-1);

        if(bx == 0){
            __shared__ float s_pred[NN*2];
            if(!obs){
                if(tid==0){
                    wait_ge(&d_epiCnt[t-1], 384);
                    wait_ge(&d_tgtCnt[t-1], 4);
                }
                __syncthreads();
                __threadfence();
                {
                    int gp = d_gateNt[t-1];
                    float4* Ht4 = (float4*)d_Ht;
                    float4* Ha4 = (float4*)d_HtaP[(t-1)&1];
                    for(int i=tid;i<NN*EDGE/4;i+=256){
                        if(gp) Ht4[i]=Ha4[i];
                        Ha4[i]=make_float4(0.f,0.f,0.f,0.f);
                    }
                }
                __threadfence();
                __syncthreads();
                if(tid==0) atomicExch(&d_mnt, t-1);
                {
                    int item = tid>>1, sub = tid&1;
                    int n = item>>1, j = item&1;
                    const float4* th4 = (const float4*)&d_thtNM[n*NODE + sub*64];
                    const float4* wp1 = (const float4*)&W_pred[j*CONC + sub*64];
                    float acc = 0.f;
                    #pragma unroll
                    for(int i=0;i<16;i++){
                        float4 a=th4[i], b=wp1[i];
                        acc += a.x*b.x + a.y*b.y + a.z*b.z + a.w*b.w;
                    }
                    const float4* hh4 = (const float4*)&d_Ht[n*EDGE + sub*128];
                    const float4* wp3 = (const float4*)&W_pred[j*CONC + NODE+CNN + sub*128];
                    #pragma unroll
                    for(int i=0;i<32;i++){
                        float4 a=hh4[i], b=wp3[i];
                        acc += a.x*b.x + a.y*b.y + a.z*b.z + a.w*b.w;
                    }
                    acc += __shfl_xor_sync(0xffffffffu, acc, 1);
                    if(sub==0) s_pred[item] = acc + d_imgpart[item] + b_pred[j];
                }
                __syncthreads();
                if(tid<NN*2){
                    float p=s_pred[tid];
                    d_cabs[tid]+=p;
                    float cr=d_crel[tid]+p; d_crel[tid]=cr;
                    d_cstepP[t&1][tid]=p;
                    int n=tid>>1, j=tid&1;
                    out[(n*PREDN + (t-TOBS))*2 + j] = cr;
                }
                __threadfence();
                __syncthreads();
                if(tid==0) atomicExch(&d_flag, t);
            }else{
                if(t==TOBS-1 && tid<NN*2){
                    int n=tid>>1, j=tid&1; int off=(n*TOBS+t)*2+j;
                    d_cabs[tid]=tabs[off]; d_crel[tid]=trel[off];
                }
                if(t>=2){
                    if(tid==0) wait_ge(&d_epiCnt[t-1], 384);
                    __syncthreads();
                    __threadfence();
                    int gp = d_gateNt[t-1];
                    float4* Ht4 = (float4*)d_Ht;
                    float4* Ha4 = (float4*)d_HtaP[(t-1)&1];
                    for(int i=tid;i<NN*EDGE/4;i+=256){
                        if(gp) Ht4[i]=Ha4[i];
                        Ha4[i]=make_float4(0.f,0.f,0.f,0.f);
                    }
                    __threadfence();
                    __syncthreads();
                    if(tid==0) atomicExch(&d_mnt, t-1);
                }
            }
        }
        else if(bx <= 384){
            int gate_n = d_gateNt[t];
            if(!gate_n){
                int row = tid>>1, half = tid&1;
                long base = (long)(m0+row)*EDGE + e0c + half*8;
                *(uint4*)&d_nh[nxt][base] = *(const uint4*)&d_nh[cur][base];
                __threadfence();
                __syncthreads();
                if(tid==0){
                    if(colTile<8) atomicAdd(&d_rowCntA[t][rowTile], 1);
                    else          atomicAdd(&d_rowCntB[t][rowTile], 1);
                    atomicAdd(&d_epiCnt[t], 1);
                }
                continue;
            }
            const __nv_bfloat16* hN = d_nh[cur];
            float C[2][4][4];
            #pragma unroll
            for(int mi=0;mi<2;mi++)
                #pragma unroll
                for(int j=0;j<4;j++){ C[mi][j][0]=0.f; C[mi][j][1]=0.f; C[mi][j][2]=0.f; C[mi][j][3]=0.f; }

            prefetch_ep(uS, nstep_in, nhist, m0, e0c, tc, tid);
            if(t>=2){
                if(tid==0) wait_ge(&d_rowCntA[t-1][rowTile], 8);
                __syncthreads();
                __threadfence();
            }
            prefetch_chunk(uS, 0u, hN, m0, g0, 0, tid);
            if(obs)
                compute_w(s_w, m0, t, true, tc, trel, tabs, nabs_in, nhist,
                          W_att_t, b_att_t, W_att_n, b_att_n, wid, lane);
            #pragma unroll
            for(int ch=0; ch<8; ch++){
                uint32_t bo = (ch&1)*BUF;
                if(ch<7){
                    if(ch==3 && t>=2){
                        if(tid==0) wait_ge(&d_rowCntB[t-1][rowTile], 8);
                        __syncthreads();
                        __threadfence();
                    }
                    prefetch_chunk(uS, ((ch+1)&1)*BUF, hN, m0, g0, (ch+1)*32, tid);
                    CPWAIT(1);
                }else{
                    CPWAIT(0);
                }
                __syncthreads();
                #pragma unroll
                for(int ktl=0; ktl<2; ktl++){
                    uint32_t koff = bo + ktl*32;
                    uint32_t ah[2][4];
                    #pragma unroll
                    for(int mi=0;mi<2;mi++)
                        LDMX4(ah[mi][0],ah[mi][1],ah[mi][2],ah[mi][3], uS + aO + (uint32_t)(mi*16*80) + koff);
                    #pragma unroll
                    for(int ng=0; ng<2; ng++){
                        uint32_t bh0,bh1,bh2,bh3;
                        LDMX4(bh0,bh1,bh2,bh3, uS + bO + (uint32_t)(ng*16*80) + koff);
                        MMA16816(C[0][ng*2],   ah[0][0],ah[0][1],ah[0][2],ah[0][3], bh0,bh2);
                        MMA16816(C[0][ng*2+1], ah[0][0],ah[0][1],ah[0][2],ah[0][3], bh1,bh3);
                        MMA16816(C[1][ng*2],   ah[1][0],ah[1][1],ah[1][2],ah[1][3], bh0,bh2);
                        MMA16816(C[1][ng*2+1], ah[1][0],ah[1][1],ah[1][2],ah[1][3], bh1,bh3);
                    }
                }
                __syncthreads();
            }

            #pragma unroll
            for(int mi=0;mi<2;mi++){
                int r0 = wm*32 + mi*16 + gid;
                #pragma unroll
                for(int jj=0;jj<4;jj++){
                    int col = wn*32 + jj*8 + tig*2;
                    *(float2*)&sC[r0*68+col]     = make_float2(C[mi][jj][0],C[mi][jj][1]);
                    *(float2*)&sC[(r0+8)*68+col] = make_float2(C[mi][jj][2],C[mi][jj][3]);
                }
            }
            if(!obs){
                if(tid==0) wait_ge(&d_flag, t);
                __syncthreads();
                __threadfence();
                compute_w(s_w, m0, t, false, tc, trel, tabs, nabs_in, nhist,
                          W_att_t, b_att_t, W_att_n, b_att_n, wid, lane);
            }
            if(tid==0 && t>=3) wait_ge(&d_mnt, t-2);
            __syncthreads();
            __threadfence();

            {
                int row = tid>>1, half = tid&1;
                int m = m0 + row;
                long base = (long)m*EDGE + e0c + half*8;
                float2 xv = *(const float2*)(dsm + OFF_EPS + row*8);
                int hist = *(const int*)(dsm + OFF_EPH + row*4);
                bool mv = obs ? (hist > (TOBS - t)) : true;
                bool un = mv;
                float wv = s_w[row];
                const float* sn = (const float*)(dsm + OFF_EPN + row*64 + half*32);
                float coldA[8];
                #pragma unroll
                for(int cc=0;cc<8;cc++) coldA[cc]=sn[cc];
                const float* g4p = &sC[row*68 + half*32];
                float hnew[8], cnew[8];
                #pragma unroll
                for(int cc=0;cc<8;cc++){
                    int gb = g0 + half*32 + cc*4;
                    float4 wA = *(const float4*)&d_WxN[gb*2];
                    float4 wB = *(const float4*)&d_WxN[gb*2+4];
                    float4 bb = *(const float4*)&d_bN[gb];
                    float gi_ = g4p[4*cc+0] + xv.x*wA.x + xv.y*wA.y + bb.x;
                    float gf  = g4p[4*cc+1] + xv.x*wA.z + xv.y*wA.w + bb.y;
                    float gg  = g4p[4*cc+2] + xv.x*wB.x + xv.y*wB.y + bb.z;
                    float go  = g4p[4*cc+3] + xv.x*wB.z + xv.y*wB.w + bb.w;
                    float c2 = sigm(gf)*coldA[cc] + sigm(gi_)*tanhf(gg);
                    hnew[cc] = sigm(go)*tanhf(c2);
                    cnew[cc] = un ? c2 : coldA[cc];
                }
                __align__(16) __nv_bfloat16 hb[8];
                if(un){
                    #pragma unroll
                    for(int cc=0;cc<8;cc++) hb[cc] = __float2bfloat16(hnew[cc]);
                }else{
                    *(uint4*)hb = *(const uint4*)&hN[base];
                    #pragma unroll
                    for(int cc=0;cc<8;cc++) hnew[cc] = __bfloat162float(hb[cc]);
                }
                *(uint4*)&d_nh[nxt][base] = *(uint4*)hb;
                *(float4*)&d_nct[base]   = make_float4(cnew[0],cnew[1],cnew[2],cnew[3]);
                *(float4*)&d_nct[base+4] = make_float4(cnew[4],cnew[5],cnew[6],cnew[7]);
                float* wout = &sWh[row*16 + half*8];
                *(float4*)&wout[0] = make_float4(wv*hnew[0],wv*hnew[1],wv*hnew[2],wv*hnew[3]);
                *(float4*)&wout[4] = make_float4(wv*hnew[4],wv*hnew[5],wv*hnew[6],wv*hnew[7]);
            }
            __syncthreads();
            if(tid < 64){
                int gi = tid>>4, col = tid&15;
                int n = m0/KK + gi;
                int lo = n*KK - m0; if(lo<0) lo=0;
                int hi2 = n*KK + KK - m0; if(hi2>128) hi2=128;
                if(lo < hi2 && n < NN){
                    float s=0.f;
                    for(int r=lo;r<hi2;r++) s += sWh[r*16+col];
                    atomicAdd(&d_HtaP[t&1][n*EDGE + e0c + col], s);
                }
            }
            __threadfence();
            __syncthreads();
            if(tid==0){
                if(colTile<8) atomicAdd(&d_rowCntA[t][rowTile], 1);
                else          atomicAdd(&d_rowCntB[t][rowTile], 1);
                atomicAdd(&d_epiCnt[t], 1);
            }
        }
        else{
            if(t>=2){
                if(tid==0) wait_ge(&d_tgtCnt[t-1], 4);
                __syncthreads();
                __threadfence();
            }
            int bj = bx - 385;
            int gate_t = d_gateTt[t];
            if(!gate_t){
                int e0 = bj*32;
                for(int i=tid;i<32*NN;i+=256){
                    int e = e0 + (i>>6), n = i&63;
                    d_thtT[nxt][e*NN+n] = d_thtT[cur][e*NN+n];
                }
                __threadfence();
                __syncthreads();
                if(tid==0) atomicAdd(&d_tgtCnt[t], 1);
                continue;
            }
            float (*As)[68]  = (float(*)[68]) (dsm);
            float (*Bs)[140] = (float(*)[140])(dsm + sizeof(float)*32*68);
            int g0t = bj*128, e0 = bj*32;
            const float* A = d_thtT[cur];
            int ty = tid>>4, tx = tid&15;
            int pb = tx*8; pb += (pb>>5)<<2;
            ULL accp[4][4];
            #pragma unroll
            for(int i=0;i<4;i++){
                #pragma unroll
                for(int j=0;j<4;j++) accp[i][j]=0ull;
            }
            for(int kt=0; kt<NODE; kt+=32){
                #pragma unroll
                for(int g=0;g<2;g++){
                    int idx = tid + g*256;
                    int k = idx>>4, nq = (idx&15)*4;
                    *(float4*)&As[k][nq] = *(const float4*)&A[(kt+k)*NN + nq];
                }
                #pragma unroll
                for(int g=0;g<4;g++){
                    int idx = tid + g*256;
                    int k = idx>>5, cq = (idx&31)*4;
                    int pc = cq + ((cq>>5)<<2);
                    *(float4*)&Bs[k][pc] = *(const float4*)&d_WhhTT[(kt+k)*GT + g0t+cq];
                }
                __syncthreads();
                #pragma unroll
                for(int k=0;k<32;k++){
                    float4 a0 = *(const float4*)&As[k][ty*4];
                    ulonglong2 bb0 = *(const ulonglong2*)&Bs[k][pb];
                    ulonglong2 bb1 = *(const ulonglong2*)&Bs[k][pb+4];
                    ULL ap;
                    PK(ap,a0.x); FMA2(accp[0][0],ap,bb0.x); FMA2(accp[0][1],ap,bb0.y); FMA2(accp[0][2],ap,bb1.x); FMA2(accp[0][3],ap,bb1.y);
                    PK(ap,a0.y); FMA2(accp[1][0],ap,bb0.x); FMA2(accp[1][1],ap,bb0.y); FMA2(accp[1][2],ap,bb1.x); FMA2(accp[1][3],ap,bb1.y);
                    PK(ap,a0.z); FMA2(accp[2][0],ap,bb0.x); FMA2(accp[2][1],ap,bb0.y); FMA2(accp[2][2],ap,bb1.x); FMA2(accp[2][3],ap,bb1.y);
                    PK(ap,a0.w); FMA2(accp[3][0],ap,bb0.x); FMA2(accp[3][1],ap,bb0.y); FMA2(accp[3][2],ap,bb1.x); FMA2(accp[3][3],ap,bb1.y);
                }
                __syncthreads();
            }
            if(!obs){
                if(tid==0){ wait_ge(&d_flag, t); }
                __syncthreads();
                __threadfence();
            }
            #pragma unroll
            for(int i=0;i<4;i++){
                int n = ty*4 + i;
                float x0, x1;
                if(obs){ int o2=(n*TOBS+t)*2; x0=tstep[o2]; x1=tstep[o2+1]; }
                else   { x0=d_cstepP[t&1][n*2]; x1=d_cstepP[t&1][n*2+1]; }
                bool tm = obs ? (thist[n] > (TOBS - t)) : true;
                #pragma unroll
                for(int c=0;c<2;c++){
                    float g4[4];
                    UPK(g4[0],g4[1],accp[i][c*2]);
                    UPK(g4[2],g4[3],accp[i][c*2+1]);
                    int rr = g0t + tx*8 + c*4;
                    #pragma unroll
                    for(int q=0;q<4;q++)
                        g4[q] += x0*d_WxT[(rr+q)*2] + x1*d_WxT[(rr+q)*2+1] + d_bT[rr+q];
                    float ig=sigm(g4[0]), fg=sigm(g4[1]), gg=tanhf(g4[2]), og=sigm(g4[3]);
                    int e = e0 + tx*2 + c;
                    float cold = d_tct[n*NODE+e];
                    float c2 = fg*cold + ig*gg;
                    float h2 = og*tanhf(c2);
                    bool un = tm;
                    float hv;
                    if(un){ d_tct[n*NODE+e]=c2; hv=h2; }
                    else  { hv = d_thtT[cur][e*NN+n]; }
                    d_thtT[nxt][e*NN+n]=hv;
                    d_thtNM[n*NODE+e]=hv;
                }
            }
            __threadfence();
            __syncthreads();
            if(tid==0) atomicAdd(&d_tgtCnt[t], 1);
        }
    }
}

// ---------------- launch ----------------
extern "C" void kernel_launch(void* const* d_in, const int* in_sizes, int n_in,
                              void* d_out, int out_size)
{
    const float* img    = (const float*)d_in[0];
    const float* tabs   = (const float*)d_in[1];
    const float* trel   = (const float*)d_in[2];
    const float* tstep  = (const float*)d_in[3];
    const float* nabs   = (const float*)d_in[4];
    const float* nstep  = (const float*)d_in[6];
    const int*   thist  = (const int*)d_in[7];
    const int*   nhist  = (const int*)d_in[8];
    const float* W_disp = (const float*)d_in[9];
    const float* b_disp = (const float*)d_in[10];
    const float* Wih_t  = (const float*)d_in[11];
    const float* Whh_t  = (const float*)d_in[12];
    const float* bih_t  = (const float*)d_in[13];
    const float* bhh_t  = (const float*)d_in[14];
    const float* Wih_n  = (const float*)d_in[15];
    const float* Whh_n  = (const float*)d_in[16];
    const float* bih_n  = (const float*)d_in[17];
    const float* bhh_n  = (const float*)d_in[18];
    const float* W_att_t= (const float*)d_in[19];
    const float* b_att_t= (const float*)d_in[20];
    const float* W_att_n= (const float*)d_in[21];
    const float* b_att_n= (const float*)d_in[22];
    const float* W_pred = (const float*)d_in[23];
    const float* b_pred = (const float*)d_in[24];
    float* out = (float*)d_out;

    static int s_attr_done = 0;
    if(!s_attr_done){
        cudaFuncSetAttribute(k_run, cudaFuncAttributeMaxDynamicSharedMemorySize, DSMEM_TOTAL);
        s_attr_done = 1;
    }

    k_zero<<<256,256>>>();
    k_tables<<<TSTEPS-1,256>>>(thist,nhist);
    k_prep<<<256,256>>>(Whh_n,Wih_n,bih_n,bhh_n,Whh_t,Wih_t,bih_t,bhh_t,
                        W_disp,b_disp,img,W_pred);
    k_run<<<NBLK,256,DSMEM_TOTAL>>>(tabs,trel,tstep,nabs,nstep,thist,nhist,
                        W_att_t,b_att_t,W_att_n,b_att_n,W_pred,b_pred,out);
}